// round 7
// baseline (speedup 1.0000x reference)
#include <cuda_runtime.h>
#include <cuda_bf16.h>
#include <cuda_fp16.h>
#include <cstdint>

#define BATCH  8
#define SLEN   1500
#define NSTATE 1024
#define NHEAD  16
#define HDIM   64
#define MROWS  (BATCH * SLEN)   // 12000

// ---------------- scratch (static device globals; no allocation) -------------
__device__ __nv_bfloat16 g_Xhi[(size_t)MROWS * NSTATE];
__device__ __nv_bfloat16 g_Xlo[(size_t)MROWS * NSTATE];
__device__ __nv_bfloat16 g_Qhi[(size_t)MROWS * NSTATE];
__device__ __nv_bfloat16 g_Qlo[(size_t)MROWS * NSTATE];
__device__ __nv_bfloat16 g_Khi[(size_t)MROWS * NSTATE];
__device__ __nv_bfloat16 g_Klo[(size_t)MROWS * NSTATE];
__device__ __half        g_Vh [(size_t)MROWS * NSTATE];
__device__ __nv_bfloat16 g_Ohi[(size_t)MROWS * NSTATE];
__device__ __nv_bfloat16 g_Olo[(size_t)MROWS * NSTATE];
__device__ __nv_bfloat16 g_Whi[4][(size_t)NSTATE * NSTATE];
__device__ __nv_bfloat16 g_Wlo[4][(size_t)NSTATE * NSTATE];

__device__ __forceinline__ uint32_t smem_u32(const void* p) {
    uint32_t a;
    asm("{ .reg .u64 t; cvta.to.shared.u64 t, %1; cvt.u32.u64 %0, t; }"
        : "=r"(a) : "l"(p));
    return a;
}

#define LDSM_X4(r0, r1, r2, r3, addr)                                            \
    asm volatile("ldmatrix.sync.aligned.m8n8.x4.shared.b16 {%0,%1,%2,%3}, [%4];" \
                 : "=r"(r0), "=r"(r1), "=r"(r2), "=r"(r3) : "r"(addr))

#define LDSM_X4_T(r0, r1, r2, r3, addr)                                          \
    asm volatile("ldmatrix.sync.aligned.m8n8.x4.trans.shared.b16 {%0,%1,%2,%3}, [%4];" \
                 : "=r"(r0), "=r"(r1), "=r"(r2), "=r"(r3) : "r"(addr))

#define MMA_BF16(c0, c1, c2, c3, a0, a1, a2, a3, b0, b1)                         \
    asm volatile("mma.sync.aligned.m16n8k16.row.col.f32.bf16.bf16.f32 "          \
                 "{%0,%1,%2,%3}, {%4,%5,%6,%7}, {%8,%9}, {%0,%1,%2,%3};"         \
                 : "+f"(c0), "+f"(c1), "+f"(c2), "+f"(c3)                        \
                 : "r"(a0), "r"(a1), "r"(a2), "r"(a3), "r"(b0), "r"(b1))

#define MMA_F16(c0, c1, c2, c3, a0, a1, a2, a3, b0, b1)                          \
    asm volatile("mma.sync.aligned.m16n8k16.row.col.f32.f16.f16.f32 "            \
                 "{%0,%1,%2,%3}, {%4,%5,%6,%7}, {%8,%9}, {%0,%1,%2,%3};"         \
                 : "+f"(c0), "+f"(c1), "+f"(c2), "+f"(c3)                        \
                 : "r"(a0), "r"(a1), "r"(a2), "r"(a3), "r"(b0), "r"(b1))

#define PACK_H2(d, vlo, vhi)                                                     \
    asm("cvt.rn.f16x2.f32 %0, %1, %2;" : "=r"(d) : "f"(vhi), "f"(vlo))

#define CP16(dst, src, nbytes)                                                   \
    asm volatile("cp.async.cg.shared.global [%0], [%1], 16, %2;"                 \
                 :: "r"(dst), "l"(src), "r"(nbytes))
#define CP_COMMIT() asm volatile("cp.async.commit_group;" ::: "memory")
#define CP_WAIT2()  asm volatile("cp.async.wait_group 2;" ::: "memory")
#define CP_WAIT1()  asm volatile("cp.async.wait_group 1;" ::: "memory")
#define CP_WAIT0()  asm volatile("cp.async.wait_group 0;" ::: "memory")

// ======================= split fp32 -> bf16 hi/lo ============================
__global__ __launch_bounds__(256) void split_bf16_kernel(
    const float* __restrict__ in0, const float* __restrict__ in1,
    const float* __restrict__ in2, const float* __restrict__ in3,
    __nv_bfloat16* __restrict__ hi, __nv_bfloat16* __restrict__ lo,
    size_t zstride, int n4)
{
    const int z = blockIdx.y;
    const float* in = (z == 0) ? in0 : (z == 1) ? in1 : (z == 2) ? in2 : in3;
    hi += z * zstride;
    lo += z * zstride;
    int i = blockIdx.x * blockDim.x + threadIdx.x;
    if (i < n4) {
        float4 v = *(const float4*)(in + (size_t)i * 4);
        __nv_bfloat16 hx = __float2bfloat16(v.x);
        __nv_bfloat16 hy = __float2bfloat16(v.y);
        __nv_bfloat16 hz = __float2bfloat16(v.z);
        __nv_bfloat16 hw = __float2bfloat16(v.w);
        __nv_bfloat162 h0 = {hx, hy}, h1 = {hz, hw};
        __nv_bfloat162 l0 = {__float2bfloat16(v.x - __bfloat162float(hx)),
                             __float2bfloat16(v.y - __bfloat162float(hy))};
        __nv_bfloat162 l1 = {__float2bfloat16(v.z - __bfloat162float(hz)),
                             __float2bfloat16(v.w - __bfloat162float(hw))};
        *(__nv_bfloat162*)(hi + (size_t)i * 4)     = h0;
        *(__nv_bfloat162*)(hi + (size_t)i * 4 + 2) = h1;
        *(__nv_bfloat162*)(lo + (size_t)i * 4)     = l0;
        *(__nv_bfloat162*)(lo + (size_t)i * 4 + 2) = l1;
    }
}

// ======== pipelined HMMA GEMM (3-stage): C = (Ahi+Alo)@(Bhi+Blo)^T + bias ====
#define GBK     32
#define GPAD    40
#define GK_ITERS (NSTATE / GBK)            // 32
#define ARR_B   (128 * GPAD * 2)           // 10240 bytes per array
#define STG_B   (4 * ARR_B)                // 40960 bytes per stage
#define GSTAGES 3
#define GSMEM   (GSTAGES * STG_B)          // 122880 bytes

template <int PASS>
__global__ __launch_bounds__(256) void hmma_gemm_kernel(
    const __nv_bfloat16* __restrict__ Ahi, const __nv_bfloat16* __restrict__ Alo,
    const __nv_bfloat16* __restrict__ Wh,  const __nv_bfloat16* __restrict__ Wl,
    const float* __restrict__ bq, const float* __restrict__ bv,
    const float* __restrict__ bo,
    __nv_bfloat16* __restrict__ qhi, __nv_bfloat16* __restrict__ qlo,
    __nv_bfloat16* __restrict__ khi, __nv_bfloat16* __restrict__ klo,
    __half* __restrict__ vh, float* __restrict__ outf, int M)
{
    extern __shared__ __align__(16) char dsm[];
    const int z = (PASS == 0) ? blockIdx.z : 3;
    const __nv_bfloat16* Bhi = Wh + (size_t)z * NSTATE * NSTATE;
    const __nv_bfloat16* Blo = Wl + (size_t)z * NSTATE * NSTATE;
    const float* bias = (PASS == 1) ? bo : ((z == 0) ? bq : (z == 2) ? bv : nullptr);

    const int tid  = threadIdx.x;
    const int wid  = tid >> 5;
    const int lane = tid & 31;
    const int m0 = blockIdx.y * 128;
    const int n0 = blockIdx.x * 128;
    const int mbase = (wid >> 2) * 64;
    const int nbase = (wid & 3) * 32;

    const uint32_t uBase = smem_u32(dsm);

    float acc[4][4][4];
#pragma unroll
    for (int i = 0; i < 4; i++)
#pragma unroll
        for (int j = 0; j < 4; j++)
#pragma unroll
            for (int q = 0; q < 4; q++) acc[i][j][q] = 0.f;

    const int lrow0 = (tid + 0)   >> 2, lc0 = (tid & 3) * 8;
    const int lrow1 = (tid + 256) >> 2;
    const int okA0 = (m0 + lrow0 < M) ? 16 : 0;
    const int okA1 = (m0 + lrow1 < M) ? 16 : 0;
    const size_t ga0 = (size_t)(m0 + lrow0) * NSTATE + lc0;
    const size_t ga1 = (size_t)(m0 + lrow1) * NSTATE + lc0;
    const size_t gb0 = (size_t)(n0 + lrow0) * NSTATE + lc0;
    const size_t gb1 = (size_t)(n0 + lrow1) * NSTATE + lc0;
    const uint32_t so0 = (uint32_t)(lrow0 * GPAD + lc0) * 2;
    const uint32_t so1 = (uint32_t)(lrow1 * GPAD + lc0) * 2;

#define ISSUE_CHUNK(kit, stg) do {                                               \
        const int k0_ = (kit) * GBK;                                             \
        const uint32_t sb = uBase + (stg) * STG_B;                               \
        CP16(sb + 0 * ARR_B + so0, Ahi + ga0 + k0_, okA0);                       \
        CP16(sb + 0 * ARR_B + so1, Ahi + ga1 + k0_, okA1);                       \
        CP16(sb + 1 * ARR_B + so0, Alo + ga0 + k0_, okA0);                       \
        CP16(sb + 1 * ARR_B + so1, Alo + ga1 + k0_, okA1);                       \
        CP16(sb + 2 * ARR_B + so0, Bhi + gb0 + k0_, 16);                         \
        CP16(sb + 2 * ARR_B + so1, Bhi + gb1 + k0_, 16);                         \
        CP16(sb + 3 * ARR_B + so0, Blo + gb0 + k0_, 16);                         \
        CP16(sb + 3 * ARR_B + so1, Blo + gb1 + k0_, 16);                         \
        CP_COMMIT();                                                             \
    } while (0)

    ISSUE_CHUNK(0, 0);
    ISSUE_CHUNK(1, 1);

    const int aRow = lane & 15, aKof = (lane >> 4) * 8;
    const int bNof = ((lane >> 4) * 8) + (lane & 7);
    const int bKof = ((lane >> 3) & 1) * 8;

    for (int kit = 0; kit < GK_ITERS; kit++) {
        if      (kit + 2 < GK_ITERS) { ISSUE_CHUNK(kit + 2, (kit + 2) % GSTAGES); CP_WAIT2(); }
        else if (kit + 1 < GK_ITERS) { CP_WAIT1(); }
        else                         { CP_WAIT0(); }
        __syncthreads();

        const uint32_t sb = uBase + (kit % GSTAGES) * STG_B;
        const uint32_t uAh = sb, uAl = sb + ARR_B, uBh = sb + 2 * ARR_B,
                       uBl = sb + 3 * ARR_B;
#pragma unroll
        for (int ks = 0; ks < 2; ks++) {
            const int kof = ks * 16;
            uint32_t ah[4][4], al[4][4];
#pragma unroll
            for (int mt = 0; mt < 4; mt++) {
                const uint32_t off =
                    (uint32_t)((mbase + mt * 16 + aRow) * GPAD + kof + aKof) * 2;
                LDSM_X4(ah[mt][0], ah[mt][1], ah[mt][2], ah[mt][3], uAh + off);
                LDSM_X4(al[mt][0], al[mt][1], al[mt][2], al[mt][3], uAl + off);
            }
            uint32_t bh[4][2], bl[4][2];
#pragma unroll
            for (int np = 0; np < 2; np++) {
                const uint32_t off =
                    (uint32_t)((nbase + np * 16 + bNof) * GPAD + kof + bKof) * 2;
                LDSM_X4(bh[np * 2][0], bh[np * 2][1], bh[np * 2 + 1][0], bh[np * 2 + 1][1],
                        uBh + off);
                LDSM_X4(bl[np * 2][0], bl[np * 2][1], bl[np * 2 + 1][0], bl[np * 2 + 1][1],
                        uBl + off);
            }
#pragma unroll
            for (int mt = 0; mt < 4; mt++)
#pragma unroll
                for (int nt = 0; nt < 4; nt++) {
                    float* c4 = acc[mt][nt];
                    MMA_BF16(c4[0], c4[1], c4[2], c4[3],
                             ah[mt][0], ah[mt][1], ah[mt][2], ah[mt][3],
                             bh[nt][0], bh[nt][1]);
                    MMA_BF16(c4[0], c4[1], c4[2], c4[3],
                             ah[mt][0], ah[mt][1], ah[mt][2], ah[mt][3],
                             bl[nt][0], bl[nt][1]);
                    MMA_BF16(c4[0], c4[1], c4[2], c4[3],
                             al[mt][0], al[mt][1], al[mt][2], al[mt][3],
                             bh[nt][0], bh[nt][1]);
                }
        }
        __syncthreads();
    }
#undef ISSUE_CHUNK

    const int lr = lane >> 2;
    const int lc = (lane & 3) * 2;
#pragma unroll
    for (int mt = 0; mt < 4; mt++) {
#pragma unroll
        for (int half_ = 0; half_ < 2; half_++) {
            const int gm = m0 + mbase + mt * 16 + half_ * 8 + lr;
            if (gm < M) {
#pragma unroll
                for (int nt = 0; nt < 4; nt++) {
                    const int gn = n0 + nbase + nt * 8 + lc;
                    float vx = acc[mt][nt][half_ * 2 + 0];
                    float vy = acc[mt][nt][half_ * 2 + 1];
                    if (bias) { vx += bias[gn]; vy += bias[gn + 1]; }
                    const size_t idx = (size_t)gm * NSTATE + gn;
                    if (PASS == 1) {
                        *(float2*)(outf + idx) = make_float2(vx, vy);
                    } else if (z == 2) {
                        __half2 hv = {__float2half_rn(vx), __float2half_rn(vy)};
                        *(__half2*)(vh + idx) = hv;
                    } else {
                        __nv_bfloat16 hx = __float2bfloat16(vx);
                        __nv_bfloat16 hy = __float2bfloat16(vy);
                        __nv_bfloat162 h = {hx, hy};
                        __nv_bfloat162 l = {__float2bfloat16(vx - __bfloat162float(hx)),
                                            __float2bfloat16(vy - __bfloat162float(hy))};
                        if (z == 0) {
                            *(__nv_bfloat162*)(qhi + idx) = h;
                            *(__nv_bfloat162*)(qlo + idx) = l;
                        } else {
                            *(__nv_bfloat162*)(khi + idx) = h;
                            *(__nv_bfloat162*)(klo + idx) = l;
                        }
                    }
                }
            }
        }
    }
}

// ================= HMMA flash attention (causal, cp.async 2-stage) ===========
#define AQ    128
#define AKV   64
#define APAD  72
#define FARR  (AKV * APAD * 2)     // 9216 bytes per K/V array
#define FSTG  (3 * FARR)           // 27648 bytes per stage (Kh, Kl, V)
#define FSMEM (2 * FSTG)           // 55296 bytes

__global__ __launch_bounds__(256, 2) void flash_hmma_kernel(
    const __nv_bfloat16* __restrict__ Qhi, const __nv_bfloat16* __restrict__ Qlo,
    const __nv_bfloat16* __restrict__ Khi, const __nv_bfloat16* __restrict__ Klo,
    const __half* __restrict__ Vh,
    __nv_bfloat16* __restrict__ Ohi, __nv_bfloat16* __restrict__ Olo)
{
    extern __shared__ __align__(16) char fsm[];
    const uint32_t uS = smem_u32(fsm);

    const int tid  = threadIdx.x;
    const int wid  = tid >> 5;
    const int lane = tid & 31;
    const int bh = blockIdx.y;
    const int b  = bh >> 4;
    const int h  = bh & 15;
    const int q0 = blockIdx.x * AQ;
    const size_t rowBase = (size_t)b * SLEN;
    const int colOff = h * HDIM;

    // ---- stage Q (128x64 hi/lo) into smem bytes [0, 36864) ----
#pragma unroll
    for (int it = 0; it < 4; it++) {
        const int id = tid + it * 256;
        const int r  = id >> 3;
        const int c  = id & 7;
        const int gq = q0 + r;
        uint4 vh = make_uint4(0, 0, 0, 0), vl = make_uint4(0, 0, 0, 0);
        if (gq < SLEN) {
            const size_t off = (rowBase + gq) * NSTATE + colOff + c * 8;
            vh = *(const uint4*)(Qhi + off);
            vl = *(const uint4*)(Qlo + off);
        }
        const int so = r * APAD + c * 8;
        *(uint4*)(fsm + so * 2)                  = vh;
        *(uint4*)(fsm + 2 * AQ * APAD + so * 2)  = vl;   // Ql at byte 36864? no: 2*128*72=18432 halves -> bytes 36864/2
    }
    __syncthreads();

    const int aRow = lane & 15, aKof = (lane >> 4) * 8;
    const int wq0 = wid * 16;
    uint32_t qh[4][4], ql[4][4];
    const uint32_t uQh = uS, uQl = uS + AQ * APAD * 2;
#pragma unroll
    for (int ks = 0; ks < 4; ks++) {
        const uint32_t off = (uint32_t)((wq0 + aRow) * APAD + ks * 16 + aKof) * 2;
        LDSM_X4(qh[ks][0], qh[ks][1], qh[ks][2], qh[ks][3], uQh + off);
        LDSM_X4(ql[ks][0], ql[ks][1], ql[ks][2], ql[ks][3], uQl + off);
    }
    __syncthreads();

#define FA_ISSUE(t, stg) do {                                                    \
        const int j0_ = (t) * AKV;                                               \
        const uint32_t sb = uS + (stg) * FSTG;                                   \
        _Pragma("unroll")                                                        \
        for (int it = 0; it < 2; it++) {                                         \
            const int id = tid + it * 256;                                       \
            const int r  = id >> 3;                                              \
            const int c  = id & 7;                                               \
            const int gk = j0_ + r;                                              \
            const int nb = (gk < SLEN) ? 16 : 0;                                 \
            const size_t off = (rowBase + gk) * NSTATE + colOff + c * 8;         \
            const uint32_t so = (uint32_t)(r * APAD + c * 8) * 2;                \
            CP16(sb + 0 * FARR + so, Khi + off, nb);                             \
            CP16(sb + 1 * FARR + so, Klo + off, nb);                             \
            CP16(sb + 2 * FARR + so, Vh  + off, nb);                             \
        }                                                                        \
        CP_COMMIT();                                                             \
    } while (0)

    const int gqa = q0 + wq0 + (lane >> 2);
    float mr0 = -1e30f, mr1 = -1e30f, l0 = 0.f, l1 = 0.f;
    float oacc[8][4];
#pragma unroll
    for (int i = 0; i < 8; i++)
#pragma unroll
        for (int q = 0; q < 4; q++) oacc[i][q] = 0.f;

    const int bNof = ((lane >> 4) * 8) + (lane & 7);
    const int bKof = ((lane >> 3) & 1) * 8;
    const int vRow = ((lane >> 3) & 1) * 8 + (lane & 7);
    const int vCof = (lane >> 4) * 8;

    const int tEnd = min(q0 + AQ - 1, SLEN - 1) / AKV;
    FA_ISSUE(0, 0);

    for (int t = 0; t <= tEnd; t++) {
        const int j0 = t * AKV;
        if (t + 1 <= tEnd) { FA_ISSUE(t + 1, (t + 1) & 1); CP_WAIT1(); }
        else               { CP_WAIT0(); }
        __syncthreads();

        const uint32_t sb = uS + (t & 1) * FSTG;
        const uint32_t uH = sb, uL = sb + FARR, uV = sb + 2 * FARR;

        if (j0 <= q0 + wq0 + 15) {
            float S[8][4];
#pragma unroll
            for (int nt = 0; nt < 8; nt++)
#pragma unroll
                for (int q = 0; q < 4; q++) S[nt][q] = 0.f;
#pragma unroll
            for (int ks = 0; ks < 4; ks++) {
                uint32_t kh[8][2], kl[8][2];
#pragma unroll
                for (int np = 0; np < 4; np++) {
                    const uint32_t off =
                        (uint32_t)((np * 16 + bNof) * APAD + ks * 16 + bKof) * 2;
                    LDSM_X4(kh[np * 2][0], kh[np * 2][1],
                            kh[np * 2 + 1][0], kh[np * 2 + 1][1], uH + off);
                    LDSM_X4(kl[np * 2][0], kl[np * 2][1],
                            kl[np * 2 + 1][0], kl[np * 2 + 1][1], uL + off);
                }
#pragma unroll
                for (int nt = 0; nt < 8; nt++) {
                    MMA_BF16(S[nt][0], S[nt][1], S[nt][2], S[nt][3],
                             qh[ks][0], qh[ks][1], qh[ks][2], qh[ks][3],
                             kh[nt][0], kh[nt][1]);
                    MMA_BF16(S[nt][0], S[nt][1], S[nt][2], S[nt][3],
                             qh[ks][0], qh[ks][1], qh[ks][2], qh[ks][3],
                             kl[nt][0], kl[nt][1]);
                    MMA_BF16(S[nt][0], S[nt][1], S[nt][2], S[nt][3],
                             ql[ks][0], ql[ks][1], ql[ks][2], ql[ks][3],
                             kh[nt][0], kh[nt][1]);
                }
            }
            float mx0 = mr0, mx1 = mr1;
            const int jc = j0 + 2 * (lane & 3);
#pragma unroll
            for (int nt = 0; nt < 8; nt++) {
#pragma unroll
                for (int q = 0; q < 4; q++) {
                    const int jg  = jc + nt * 8 + (q & 1);
                    const int row = (q < 2) ? gqa : gqa + 8;
                    const bool ok = (jg <= row) && (jg < SLEN);
                    const float sv = ok ? S[nt][q] * 0.125f : -1e30f;
                    S[nt][q] = sv;
                    if (q < 2) mx0 = fmaxf(mx0, sv); else mx1 = fmaxf(mx1, sv);
                }
            }
            mx0 = fmaxf(mx0, __shfl_xor_sync(0xffffffffu, mx0, 1));
            mx0 = fmaxf(mx0, __shfl_xor_sync(0xffffffffu, mx0, 2));
            mx1 = fmaxf(mx1, __shfl_xor_sync(0xffffffffu, mx1, 1));
            mx1 = fmaxf(mx1, __shfl_xor_sync(0xffffffffu, mx1, 2));
            const float corr0 = __expf(mr0 - mx0);
            const float corr1 = __expf(mr1 - mx1);
            mr0 = mx0; mr1 = mx1;
            float ps0 = 0.f, ps1 = 0.f;
#pragma unroll
            for (int nt = 0; nt < 8; nt++) {
#pragma unroll
                for (int q = 0; q < 4; q++) {
                    const float p = __expf(S[nt][q] - ((q < 2) ? mx0 : mx1));
                    S[nt][q] = p;
                    if (q < 2) ps0 += p; else ps1 += p;
                }
            }
            ps0 += __shfl_xor_sync(0xffffffffu, ps0, 1);
            ps0 += __shfl_xor_sync(0xffffffffu, ps0, 2);
            ps1 += __shfl_xor_sync(0xffffffffu, ps1, 1);
            ps1 += __shfl_xor_sync(0xffffffffu, ps1, 2);
            l0 = l0 * corr0 + ps0;
            l1 = l1 * corr1 + ps1;
#pragma unroll
            for (int nt = 0; nt < 8; nt++) {
                oacc[nt][0] *= corr0; oacc[nt][1] *= corr0;
                oacc[nt][2] *= corr1; oacc[nt][3] *= corr1;
            }
#pragma unroll
            for (int ks2 = 0; ks2 < 4; ks2++) {
                uint32_t a0, a1, a2, a3;
                PACK_H2(a0, S[2 * ks2][0],     S[2 * ks2][1]);
                PACK_H2(a1, S[2 * ks2][2],     S[2 * ks2][3]);
                PACK_H2(a2, S[2 * ks2 + 1][0], S[2 * ks2 + 1][1]);
                PACK_H2(a3, S[2 * ks2 + 1][2], S[2 * ks2 + 1][3]);
#pragma unroll
                for (int dp = 0; dp < 4; dp++) {
                    uint32_t v0, v1, v2, v3;
                    const uint32_t off =
                        (uint32_t)((ks2 * 16 + vRow) * APAD + dp * 16 + vCof) * 2;
                    LDSM_X4_T(v0, v1, v2, v3, uV + off);
                    MMA_F16(oacc[2 * dp][0], oacc[2 * dp][1],
                            oacc[2 * dp][2], oacc[2 * dp][3],
                            a0, a1, a2, a3, v0, v1);
                    MMA_F16(oacc[2 * dp + 1][0], oacc[2 * dp + 1][1],
                            oacc[2 * dp + 1][2], oacc[2 * dp + 1][3],
                            a0, a1, a2, a3, v2, v3);
                }
            }
        }
        __syncthreads();
    }
#undef FA_ISSUE

    const float inv0 = (l0 > 0.f) ? 1.f / l0 : 0.f;
    const float inv1 = (l1 > 0.f) ? 1.f / l1 : 0.f;
#pragma unroll
    for (int nt = 0; nt < 8; nt++) {
        const int d = colOff + nt * 8 + 2 * (lane & 3);
        if (gqa < SLEN) {
            const float vx = oacc[nt][0] * inv0;
            const float vy = oacc[nt][1] * inv0;
            __nv_bfloat16 hx = __float2bfloat16(vx), hy = __float2bfloat16(vy);
            __nv_bfloat162 hh = {hx, hy};
            __nv_bfloat162 ll = {__float2bfloat16(vx - __bfloat162float(hx)),
                                 __float2bfloat16(vy - __bfloat162float(hy))};
            const size_t idx = (rowBase + gqa) * NSTATE + d;
            *(__nv_bfloat162*)(Ohi + idx) = hh;
            *(__nv_bfloat162*)(Olo + idx) = ll;
        }
        if (gqa + 8 < SLEN) {
            const float vx = oacc[nt][2] * inv1;
            const float vy = oacc[nt][3] * inv1;
            __nv_bfloat16 hx = __float2bfloat16(vx), hy = __float2bfloat16(vy);
            __nv_bfloat162 hh = {hx, hy};
            __nv_bfloat162 ll = {__float2bfloat16(vx - __bfloat162float(hx)),
                                 __float2bfloat16(vy - __bfloat162float(hy))};
            const size_t idx = (rowBase + gqa + 8) * NSTATE + d;
            *(__nv_bfloat162*)(Ohi + idx) = hh;
            *(__nv_bfloat162*)(Olo + idx) = ll;
        }
    }
}

// ---------------- launch -----------------------------------------------------
extern "C" void kernel_launch(void* const* d_in, const int* in_sizes, int n_in,
                              void* d_out, int out_size)
{
    const float* x  = (const float*)d_in[0];
    const float* Wq = (const float*)d_in[2];
    const float* bq = (const float*)d_in[3];
    const float* Wk = (const float*)d_in[4];
    const float* Wv = (const float*)d_in[5];
    const float* bv = (const float*)d_in[6];
    const float* Wo = (const float*)d_in[7];
    const float* bo = (const float*)d_in[8];
    float* out = (float*)d_out;

    __nv_bfloat16 *xhi, *xlo, *qhi, *qlo, *khi, *klo, *ohi, *olo, *whi, *wlo;
    __half* vh;
    cudaGetSymbolAddress((void**)&xhi, g_Xhi);
    cudaGetSymbolAddress((void**)&xlo, g_Xlo);
    cudaGetSymbolAddress((void**)&qhi, g_Qhi);
    cudaGetSymbolAddress((void**)&qlo, g_Qlo);
    cudaGetSymbolAddress((void**)&khi, g_Khi);
    cudaGetSymbolAddress((void**)&klo, g_Klo);
    cudaGetSymbolAddress((void**)&vh,  g_Vh);
    cudaGetSymbolAddress((void**)&ohi, g_Ohi);
    cudaGetSymbolAddress((void**)&olo, g_Olo);
    cudaGetSymbolAddress((void**)&whi, g_Whi);
    cudaGetSymbolAddress((void**)&wlo, g_Wlo);
    const size_t WSZ = (size_t)NSTATE * NSTATE;

    cudaFuncSetAttribute(hmma_gemm_kernel<0>,
                         cudaFuncAttributeMaxDynamicSharedMemorySize, GSMEM);
    cudaFuncSetAttribute(hmma_gemm_kernel<1>,
                         cudaFuncAttributeMaxDynamicSharedMemorySize, GSMEM);
    cudaFuncSetAttribute(flash_hmma_kernel,
                         cudaFuncAttributeMaxDynamicSharedMemorySize, FSMEM);

    const int xn4 = MROWS * NSTATE / 4;
    const int wn4 = NSTATE * NSTATE / 4;
    split_bf16_kernel<<<dim3((xn4 + 255) / 256, 1), 256>>>(
        x, nullptr, nullptr, nullptr, xhi, xlo, 0, xn4);
    split_bf16_kernel<<<dim3((wn4 + 255) / 256, 4), 256>>>(
        Wq, Wk, Wv, Wo, whi, wlo, WSZ, wn4);

    const dim3 qkvgrid(NSTATE / 128, (MROWS + 127) / 128, 3);
    hmma_gemm_kernel<0><<<qkvgrid, 256, GSMEM>>>(
        xhi, xlo, whi, wlo, bq, bv, bo, qhi, qlo, khi, klo, vh, nullptr, MROWS);

    const dim3 agrid((SLEN + AQ - 1) / AQ, BATCH * NHEAD);
    flash_hmma_kernel<<<agrid, 256, FSMEM>>>(qhi, qlo, khi, klo, vh, ohi, olo);

    const dim3 ogrid(NSTATE / 128, (MROWS + 127) / 128, 1);
    hmma_gemm_kernel<1><<<ogrid, 256, GSMEM>>>(
        ohi, olo, whi, wlo, bq, bv, bo, nullptr, nullptr, nullptr, nullptr, vh, out, MROWS);
}

// round 8
// speedup vs baseline: 1.3585x; 1.3585x over previous
#include <cuda_runtime.h>
#include <cuda_bf16.h>
#include <cuda_fp16.h>
#include <cstdint>

#define BATCH  8
#define SLEN   1500
#define NSTATE 1024
#define NHEAD  16
#define HDIM   64
#define MROWS  (BATCH * SLEN)   // 12000

// ---------------- scratch (static device globals; no allocation) -------------
__device__ __nv_bfloat16 g_Xhi[(size_t)MROWS * NSTATE];
__device__ __nv_bfloat16 g_Xlo[(size_t)MROWS * NSTATE];
__device__ __half        g_Xh [(size_t)MROWS * NSTATE];
__device__ __nv_bfloat16 g_Qhi[(size_t)MROWS * NSTATE];
__device__ __nv_bfloat16 g_Qlo[(size_t)MROWS * NSTATE];
__device__ __nv_bfloat16 g_Khi[(size_t)MROWS * NSTATE];
__device__ __nv_bfloat16 g_Klo[(size_t)MROWS * NSTATE];
__device__ __half        g_Vh [(size_t)MROWS * NSTATE];
__device__ __half        g_Oh [(size_t)MROWS * NSTATE];
__device__ __nv_bfloat16 g_Whi[2][(size_t)NSTATE * NSTATE];
__device__ __nv_bfloat16 g_Wlo[2][(size_t)NSTATE * NSTATE];
__device__ __half        g_Wvh[(size_t)NSTATE * NSTATE];
__device__ __half        g_Woh[(size_t)NSTATE * NSTATE];

__device__ __forceinline__ uint32_t smem_u32(const void* p) {
    uint32_t a;
    asm("{ .reg .u64 t; cvta.to.shared.u64 t, %1; cvt.u32.u64 %0, t; }"
        : "=r"(a) : "l"(p));
    return a;
}

#define LDSM_X4(r0, r1, r2, r3, addr)                                            \
    asm volatile("ldmatrix.sync.aligned.m8n8.x4.shared.b16 {%0,%1,%2,%3}, [%4];" \
                 : "=r"(r0), "=r"(r1), "=r"(r2), "=r"(r3) : "r"(addr))

#define LDSM_X4_T(r0, r1, r2, r3, addr)                                          \
    asm volatile("ldmatrix.sync.aligned.m8n8.x4.trans.shared.b16 {%0,%1,%2,%3}, [%4];" \
                 : "=r"(r0), "=r"(r1), "=r"(r2), "=r"(r3) : "r"(addr))

#define MMA_BF16(c0, c1, c2, c3, a0, a1, a2, a3, b0, b1)                         \
    asm volatile("mma.sync.aligned.m16n8k16.row.col.f32.bf16.bf16.f32 "          \
                 "{%0,%1,%2,%3}, {%4,%5,%6,%7}, {%8,%9}, {%0,%1,%2,%3};"         \
                 : "+f"(c0), "+f"(c1), "+f"(c2), "+f"(c3)                        \
                 : "r"(a0), "r"(a1), "r"(a2), "r"(a3), "r"(b0), "r"(b1))

#define MMA_F16(c0, c1, c2, c3, a0, a1, a2, a3, b0, b1)                          \
    asm volatile("mma.sync.aligned.m16n8k16.row.col.f32.f16.f16.f32 "            \
                 "{%0,%1,%2,%3}, {%4,%5,%6,%7}, {%8,%9}, {%0,%1,%2,%3};"         \
                 : "+f"(c0), "+f"(c1), "+f"(c2), "+f"(c3)                        \
                 : "r"(a0), "r"(a1), "r"(a2), "r"(a3), "r"(b0), "r"(b1))

#define PACK_H2(d, vlo, vhi)                                                     \
    asm("cvt.rn.f16x2.f32 %0, %1, %2;" : "=r"(d) : "f"(vhi), "f"(vlo))

#define CP16(dst, src, nbytes)                                                   \
    asm volatile("cp.async.cg.shared.global [%0], [%1], 16, %2;"                 \
                 :: "r"(dst), "l"(src), "r"(nbytes))
#define CP_COMMIT() asm volatile("cp.async.commit_group;" ::: "memory")
#define CP_WAIT1()  asm volatile("cp.async.wait_group 1;" ::: "memory")
#define CP_WAIT0()  asm volatile("cp.async.wait_group 0;" ::: "memory")

// ======================= split fp32 -> bf16 hi/lo ============================
__global__ __launch_bounds__(256) void split_bf16_kernel(
    const float* __restrict__ in0, const float* __restrict__ in1,
    const float* __restrict__ in2,
    __nv_bfloat16* __restrict__ hi, __nv_bfloat16* __restrict__ lo,
    size_t zstride, int n4)
{
    const int z = blockIdx.y;
    const float* in = (z == 0) ? in0 : (z == 1) ? in1 : in2;
    hi += z * zstride;
    lo += z * zstride;
    int i = blockIdx.x * blockDim.x + threadIdx.x;
    if (i < n4) {
        float4 v = *(const float4*)(in + (size_t)i * 4);
        __nv_bfloat16 hx = __float2bfloat16(v.x);
        __nv_bfloat16 hy = __float2bfloat16(v.y);
        __nv_bfloat16 hz = __float2bfloat16(v.z);
        __nv_bfloat16 hw = __float2bfloat16(v.w);
        __nv_bfloat162 h0 = {hx, hy}, h1 = {hz, hw};
        __nv_bfloat162 l0 = {__float2bfloat16(v.x - __bfloat162float(hx)),
                             __float2bfloat16(v.y - __bfloat162float(hy))};
        __nv_bfloat162 l1 = {__float2bfloat16(v.z - __bfloat162float(hz)),
                             __float2bfloat16(v.w - __bfloat162float(hw))};
        *(__nv_bfloat162*)(hi + (size_t)i * 4)     = h0;
        *(__nv_bfloat162*)(hi + (size_t)i * 4 + 2) = h1;
        *(__nv_bfloat162*)(lo + (size_t)i * 4)     = l0;
        *(__nv_bfloat162*)(lo + (size_t)i * 4 + 2) = l1;
    }
}

// ======================= convert fp32 -> fp16 ================================
__global__ __launch_bounds__(256) void cvt_f16_kernel(
    const float* __restrict__ in0, const float* __restrict__ in1,
    __half* __restrict__ o0, __half* __restrict__ o1, int n4)
{
    const int z = blockIdx.y;
    const float* in = (z == 0) ? in0 : in1;
    __half* o = (z == 0) ? o0 : o1;
    int i = blockIdx.x * blockDim.x + threadIdx.x;
    if (i < n4) {
        float4 v = *(const float4*)(in + (size_t)i * 4);
        __half2 h0 = {__float2half_rn(v.x), __float2half_rn(v.y)};
        __half2 h1 = {__float2half_rn(v.z), __float2half_rn(v.w)};
        *(__half2*)(o + (size_t)i * 4)     = h0;
        *(__half2*)(o + (size_t)i * 4 + 2) = h1;
    }
}

// ===== split-bf16 HMMA GEMM (2-stage cp.async): Q/K projections ==============
#define GBK     32
#define GPAD    40
#define GK_ITERS (NSTATE / GBK)            // 32
#define ARR_B   (128 * GPAD * 2)           // 10240 bytes per array
#define STG4_B  (4 * ARR_B)                // 40960 bytes per stage
#define GSMEM4  (2 * STG4_B)               // 81920 bytes

__global__ __launch_bounds__(256) void gemm_qk_kernel(
    const __nv_bfloat16* __restrict__ Ahi, const __nv_bfloat16* __restrict__ Alo,
    const __nv_bfloat16* __restrict__ Wh,  const __nv_bfloat16* __restrict__ Wl,
    const float* __restrict__ bq,
    __nv_bfloat16* __restrict__ qhi, __nv_bfloat16* __restrict__ qlo,
    __nv_bfloat16* __restrict__ khi, __nv_bfloat16* __restrict__ klo, int M)
{
    extern __shared__ __align__(16) char dsm[];
    const int z = blockIdx.z;                    // 0: Q(+bq), 1: K
    const __nv_bfloat16* Bhi = Wh + (size_t)z * NSTATE * NSTATE;
    const __nv_bfloat16* Blo = Wl + (size_t)z * NSTATE * NSTATE;
    const float* bias = (z == 0) ? bq : nullptr;

    const int tid  = threadIdx.x;
    const int wid  = tid >> 5;
    const int lane = tid & 31;
    const int m0 = blockIdx.y * 128;
    const int n0 = blockIdx.x * 128;
    const int mbase = (wid >> 2) * 64;
    const int nbase = (wid & 3) * 32;
    const uint32_t uBase = smem_u32(dsm);

    float acc[4][4][4];
#pragma unroll
    for (int i = 0; i < 4; i++)
#pragma unroll
        for (int j = 0; j < 4; j++)
#pragma unroll
            for (int q = 0; q < 4; q++) acc[i][j][q] = 0.f;

    const int lrow0 = (tid + 0)   >> 2, lc0 = (tid & 3) * 8;
    const int lrow1 = (tid + 256) >> 2;
    const int okA0 = (m0 + lrow0 < M) ? 16 : 0;
    const int okA1 = (m0 + lrow1 < M) ? 16 : 0;
    const size_t ga0 = (size_t)(m0 + lrow0) * NSTATE + lc0;
    const size_t ga1 = (size_t)(m0 + lrow1) * NSTATE + lc0;
    const size_t gb0 = (size_t)(n0 + lrow0) * NSTATE + lc0;
    const size_t gb1 = (size_t)(n0 + lrow1) * NSTATE + lc0;
    const uint32_t so0 = (uint32_t)(lrow0 * GPAD + lc0) * 2;
    const uint32_t so1 = (uint32_t)(lrow1 * GPAD + lc0) * 2;

#define ISSUE4(kit, stg) do {                                                    \
        const int k0_ = (kit) * GBK;                                             \
        const uint32_t sb = uBase + (stg) * STG4_B;                              \
        CP16(sb + 0 * ARR_B + so0, Ahi + ga0 + k0_, okA0);                       \
        CP16(sb + 0 * ARR_B + so1, Ahi + ga1 + k0_, okA1);                       \
        CP16(sb + 1 * ARR_B + so0, Alo + ga0 + k0_, okA0);                       \
        CP16(sb + 1 * ARR_B + so1, Alo + ga1 + k0_, okA1);                       \
        CP16(sb + 2 * ARR_B + so0, Bhi + gb0 + k0_, 16);                         \
        CP16(sb + 2 * ARR_B + so1, Bhi + gb1 + k0_, 16);                         \
        CP16(sb + 3 * ARR_B + so0, Blo + gb0 + k0_, 16);                         \
        CP16(sb + 3 * ARR_B + so1, Blo + gb1 + k0_, 16);                         \
        CP_COMMIT();                                                             \
    } while (0)

    ISSUE4(0, 0);

    const int aRow = lane & 15, aKof = (lane >> 4) * 8;
    const int bNof = ((lane >> 4) * 8) + (lane & 7);
    const int bKof = ((lane >> 3) & 1) * 8;

    for (int kit = 0; kit < GK_ITERS; kit++) {
        if (kit + 1 < GK_ITERS) { ISSUE4(kit + 1, (kit + 1) & 1); CP_WAIT1(); }
        else                    { CP_WAIT0(); }
        __syncthreads();

        const uint32_t sb = uBase + (kit & 1) * STG4_B;
        const uint32_t uAh = sb, uAl = sb + ARR_B, uBh = sb + 2 * ARR_B,
                       uBl = sb + 3 * ARR_B;
#pragma unroll
        for (int ks = 0; ks < 2; ks++) {
            const int kof = ks * 16;
            uint32_t ah[4][4], al[4][4];
#pragma unroll
            for (int mt = 0; mt < 4; mt++) {
                const uint32_t off =
                    (uint32_t)((mbase + mt * 16 + aRow) * GPAD + kof + aKof) * 2;
                LDSM_X4(ah[mt][0], ah[mt][1], ah[mt][2], ah[mt][3], uAh + off);
                LDSM_X4(al[mt][0], al[mt][1], al[mt][2], al[mt][3], uAl + off);
            }
            uint32_t bh[4][2], bl[4][2];
#pragma unroll
            for (int np = 0; np < 2; np++) {
                const uint32_t off =
                    (uint32_t)((nbase + np * 16 + bNof) * GPAD + kof + bKof) * 2;
                LDSM_X4(bh[np * 2][0], bh[np * 2][1], bh[np * 2 + 1][0], bh[np * 2 + 1][1],
                        uBh + off);
                LDSM_X4(bl[np * 2][0], bl[np * 2][1], bl[np * 2 + 1][0], bl[np * 2 + 1][1],
                        uBl + off);
            }
#pragma unroll
            for (int mt = 0; mt < 4; mt++)
#pragma unroll
                for (int nt = 0; nt < 4; nt++) {
                    float* c4 = acc[mt][nt];
                    MMA_BF16(c4[0], c4[1], c4[2], c4[3],
                             ah[mt][0], ah[mt][1], ah[mt][2], ah[mt][3],
                             bh[nt][0], bh[nt][1]);
                    MMA_BF16(c4[0], c4[1], c4[2], c4[3],
                             ah[mt][0], ah[mt][1], ah[mt][2], ah[mt][3],
                             bl[nt][0], bl[nt][1]);
                    MMA_BF16(c4[0], c4[1], c4[2], c4[3],
                             al[mt][0], al[mt][1], al[mt][2], al[mt][3],
                             bh[nt][0], bh[nt][1]);
                }
        }
        __syncthreads();
    }
#undef ISSUE4

    const int lr = lane >> 2;
    const int lc = (lane & 3) * 2;
#pragma unroll
    for (int mt = 0; mt < 4; mt++) {
#pragma unroll
        for (int half_ = 0; half_ < 2; half_++) {
            const int gm = m0 + mbase + mt * 16 + half_ * 8 + lr;
            if (gm < M) {
#pragma unroll
                for (int nt = 0; nt < 4; nt++) {
                    const int gn = n0 + nbase + nt * 8 + lc;
                    float vx = acc[mt][nt][half_ * 2 + 0];
                    float vy = acc[mt][nt][half_ * 2 + 1];
                    if (bias) { vx += bias[gn]; vy += bias[gn + 1]; }
                    const size_t idx = (size_t)gm * NSTATE + gn;
                    __nv_bfloat16 hx = __float2bfloat16(vx);
                    __nv_bfloat16 hy = __float2bfloat16(vy);
                    __nv_bfloat162 h = {hx, hy};
                    __nv_bfloat162 l = {__float2bfloat16(vx - __bfloat162float(hx)),
                                        __float2bfloat16(vy - __bfloat162float(hy))};
                    if (z == 0) {
                        *(__nv_bfloat162*)(qhi + idx) = h;
                        *(__nv_bfloat162*)(qlo + idx) = l;
                    } else {
                        *(__nv_bfloat162*)(khi + idx) = h;
                        *(__nv_bfloat162*)(klo + idx) = l;
                    }
                }
            }
        }
    }
}

// ===== fp16 single-MMA GEMM (2-stage cp.async): V and O projections ==========
#define STG2_B  (2 * ARR_B)                // 20480 bytes per stage
#define GSMEM2  (2 * STG2_B)               // 40960 bytes

template <int OUTF32>
__global__ __launch_bounds__(256) void gemm_f16_kernel(
    const __half* __restrict__ A, const __half* __restrict__ B,
    const float* __restrict__ bias,
    __half* __restrict__ outh, float* __restrict__ outf, int M)
{
    extern __shared__ __align__(16) char dsm[];
    const int tid  = threadIdx.x;
    const int wid  = tid >> 5;
    const int lane = tid & 31;
    const int m0 = blockIdx.y * 128;
    const int n0 = blockIdx.x * 128;
    const int mbase = (wid >> 2) * 64;
    const int nbase = (wid & 3) * 32;
    const uint32_t uBase = smem_u32(dsm);

    float acc[4][4][4];
#pragma unroll
    for (int i = 0; i < 4; i++)
#pragma unroll
        for (int j = 0; j < 4; j++)
#pragma unroll
            for (int q = 0; q < 4; q++) acc[i][j][q] = 0.f;

    const int lrow0 = (tid + 0)   >> 2, lc0 = (tid & 3) * 8;
    const int lrow1 = (tid + 256) >> 2;
    const int okA0 = (m0 + lrow0 < M) ? 16 : 0;
    const int okA1 = (m0 + lrow1 < M) ? 16 : 0;
    const size_t ga0 = (size_t)(m0 + lrow0) * NSTATE + lc0;
    const size_t ga1 = (size_t)(m0 + lrow1) * NSTATE + lc0;
    const size_t gb0 = (size_t)(n0 + lrow0) * NSTATE + lc0;
    const size_t gb1 = (size_t)(n0 + lrow1) * NSTATE + lc0;
    const uint32_t so0 = (uint32_t)(lrow0 * GPAD + lc0) * 2;
    const uint32_t so1 = (uint32_t)(lrow1 * GPAD + lc0) * 2;

#define ISSUE2(kit, stg) do {                                                    \
        const int k0_ = (kit) * GBK;                                             \
        const uint32_t sb = uBase + (stg) * STG2_B;                              \
        CP16(sb + 0 * ARR_B + so0, A + ga0 + k0_, okA0);                         \
        CP16(sb + 0 * ARR_B + so1, A + ga1 + k0_, okA1);                         \
        CP16(sb + 1 * ARR_B + so0, B + gb0 + k0_, 16);                           \
        CP16(sb + 1 * ARR_B + so1, B + gb1 + k0_, 16);                           \
        CP_COMMIT();                                                             \
    } while (0)

    ISSUE2(0, 0);

    const int aRow = lane & 15, aKof = (lane >> 4) * 8;
    const int bNof = ((lane >> 4) * 8) + (lane & 7);
    const int bKof = ((lane >> 3) & 1) * 8;

    for (int kit = 0; kit < GK_ITERS; kit++) {
        if (kit + 1 < GK_ITERS) { ISSUE2(kit + 1, (kit + 1) & 1); CP_WAIT1(); }
        else                    { CP_WAIT0(); }
        __syncthreads();

        const uint32_t sb = uBase + (kit & 1) * STG2_B;
        const uint32_t uA = sb, uB = sb + ARR_B;
#pragma unroll
        for (int ks = 0; ks < 2; ks++) {
            const int kof = ks * 16;
            uint32_t a[4][4];
#pragma unroll
            for (int mt = 0; mt < 4; mt++) {
                const uint32_t off =
                    (uint32_t)((mbase + mt * 16 + aRow) * GPAD + kof + aKof) * 2;
                LDSM_X4(a[mt][0], a[mt][1], a[mt][2], a[mt][3], uA + off);
            }
            uint32_t b[4][2];
#pragma unroll
            for (int np = 0; np < 2; np++) {
                const uint32_t off =
                    (uint32_t)((nbase + np * 16 + bNof) * GPAD + kof + bKof) * 2;
                LDSM_X4(b[np * 2][0], b[np * 2][1], b[np * 2 + 1][0], b[np * 2 + 1][1],
                        uB + off);
            }
#pragma unroll
            for (int mt = 0; mt < 4; mt++)
#pragma unroll
                for (int nt = 0; nt < 4; nt++) {
                    float* c4 = acc[mt][nt];
                    MMA_F16(c4[0], c4[1], c4[2], c4[3],
                            a[mt][0], a[mt][1], a[mt][2], a[mt][3],
                            b[nt][0], b[nt][1]);
                }
        }
        __syncthreads();
    }
#undef ISSUE2

    const int lr = lane >> 2;
    const int lc = (lane & 3) * 2;
#pragma unroll
    for (int mt = 0; mt < 4; mt++) {
#pragma unroll
        for (int half_ = 0; half_ < 2; half_++) {
            const int gm = m0 + mbase + mt * 16 + half_ * 8 + lr;
            if (gm < M) {
#pragma unroll
                for (int nt = 0; nt < 4; nt++) {
                    const int gn = n0 + nbase + nt * 8 + lc;
                    float vx = acc[mt][nt][half_ * 2 + 0];
                    float vy = acc[mt][nt][half_ * 2 + 1];
                    if (bias) { vx += bias[gn]; vy += bias[gn + 1]; }
                    const size_t idx = (size_t)gm * NSTATE + gn;
                    if (OUTF32) {
                        *(float2*)(outf + idx) = make_float2(vx, vy);
                    } else {
                        __half2 hv = {__float2half_rn(vx), __float2half_rn(vy)};
                        *(__half2*)(outh + idx) = hv;
                    }
                }
            }
        }
    }
}

// ================= HMMA flash attention (causal, cp.async 2-stage) ===========
#define AQ    128
#define AKV   64
#define APAD  72
#define FARR  (AKV * APAD * 2)     // 9216 bytes per K/V array
#define FSTG  (3 * FARR)           // 27648 bytes per stage (Kh, Kl, V)
#define FSMEM (2 * FSTG)           // 55296 bytes

__global__ __launch_bounds__(256, 2) void flash_hmma_kernel(
    const __nv_bfloat16* __restrict__ Qhi, const __nv_bfloat16* __restrict__ Qlo,
    const __nv_bfloat16* __restrict__ Khi, const __nv_bfloat16* __restrict__ Klo,
    const __half* __restrict__ Vh, __half* __restrict__ Oh)
{
    extern __shared__ __align__(16) char fsm[];
    const uint32_t uS = smem_u32(fsm);

    const int tid  = threadIdx.x;
    const int wid  = tid >> 5;
    const int lane = tid & 31;
    const int bh = blockIdx.y;
    const int b  = bh >> 4;
    const int h  = bh & 15;
    // longest (highest q0) CTAs first: better tail scheduling for causal work
    const int q0 = (gridDim.x - 1 - blockIdx.x) * AQ;
    const size_t rowBase = (size_t)b * SLEN;
    const int colOff = h * HDIM;

    // ---- stage Q (128x64 hi/lo) ----
#pragma unroll
    for (int it = 0; it < 4; it++) {
        const int id = tid + it * 256;
        const int r  = id >> 3;
        const int c  = id & 7;
        const int gq = q0 + r;
        uint4 vh = make_uint4(0, 0, 0, 0), vl = make_uint4(0, 0, 0, 0);
        if (gq < SLEN) {
            const size_t off = (rowBase + gq) * NSTATE + colOff + c * 8;
            vh = *(const uint4*)(Qhi + off);
            vl = *(const uint4*)(Qlo + off);
        }
        const int so = r * APAD + c * 8;
        *(uint4*)(fsm + so * 2)                 = vh;
        *(uint4*)(fsm + 2 * AQ * APAD + so * 2) = vl;
    }
    __syncthreads();

    const int aRow = lane & 15, aKof = (lane >> 4) * 8;
    const int wq0 = wid * 16;
    uint32_t qh[4][4], ql[4][4];
    const uint32_t uQh = uS, uQl = uS + AQ * APAD * 2;
#pragma unroll
    for (int ks = 0; ks < 4; ks++) {
        const uint32_t off = (uint32_t)((wq0 + aRow) * APAD + ks * 16 + aKof) * 2;
        LDSM_X4(qh[ks][0], qh[ks][1], qh[ks][2], qh[ks][3], uQh + off);
        LDSM_X4(ql[ks][0], ql[ks][1], ql[ks][2], ql[ks][3], uQl + off);
    }
    __syncthreads();

#define FA_ISSUE(t, stg) do {                                                    \
        const int j0_ = (t) * AKV;                                               \
        const uint32_t sb = uS + (stg) * FSTG;                                   \
        _Pragma("unroll")                                                        \
        for (int it = 0; it < 2; it++) {                                         \
            const int id = tid + it * 256;                                       \
            const int r  = id >> 3;                                              \
            const int c  = id & 7;                                               \
            const int gk = j0_ + r;                                              \
            const int nb = (gk < SLEN) ? 16 : 0;                                 \
            const size_t off = (rowBase + gk) * NSTATE + colOff + c * 8;         \
            const uint32_t so = (uint32_t)(r * APAD + c * 8) * 2;                \
            CP16(sb + 0 * FARR + so, Khi + off, nb);                             \
            CP16(sb + 1 * FARR + so, Klo + off, nb);                             \
            CP16(sb + 2 * FARR + so, Vh  + off, nb);                             \
        }                                                                        \
        CP_COMMIT();                                                             \
    } while (0)

    const int gqa = q0 + wq0 + (lane >> 2);
    float mr0 = -1e30f, mr1 = -1e30f, l0 = 0.f, l1 = 0.f;
    float oacc[8][4];
#pragma unroll
    for (int i = 0; i < 8; i++)
#pragma unroll
        for (int q = 0; q < 4; q++) oacc[i][q] = 0.f;

    const int bNof = ((lane >> 4) * 8) + (lane & 7);
    const int bKof = ((lane >> 3) & 1) * 8;
    const int vRow = ((lane >> 3) & 1) * 8 + (lane & 7);
    const int vCof = (lane >> 4) * 8;

    const int tEnd = min(q0 + AQ - 1, SLEN - 1) / AKV;
    FA_ISSUE(0, 0);

    for (int t = 0; t <= tEnd; t++) {
        const int j0 = t * AKV;
        if (t + 1 <= tEnd) { FA_ISSUE(t + 1, (t + 1) & 1); CP_WAIT1(); }
        else               { CP_WAIT0(); }
        __syncthreads();

        const uint32_t sb = uS + (t & 1) * FSTG;
        const uint32_t uH = sb, uL = sb + FARR, uV = sb + 2 * FARR;

        if (j0 <= q0 + wq0 + 15) {
            float S[8][4];
#pragma unroll
            for (int nt = 0; nt < 8; nt++)
#pragma unroll
                for (int q = 0; q < 4; q++) S[nt][q] = 0.f;
#pragma unroll
            for (int ks = 0; ks < 4; ks++) {
                uint32_t kh[8][2], kl[8][2];
#pragma unroll
                for (int np = 0; np < 4; np++) {
                    const uint32_t off =
                        (uint32_t)((np * 16 + bNof) * APAD + ks * 16 + bKof) * 2;
                    LDSM_X4(kh[np * 2][0], kh[np * 2][1],
                            kh[np * 2 + 1][0], kh[np * 2 + 1][1], uH + off);
                    LDSM_X4(kl[np * 2][0], kl[np * 2][1],
                            kl[np * 2 + 1][0], kl[np * 2 + 1][1], uL + off);
                }
#pragma unroll
                for (int nt = 0; nt < 8; nt++) {
                    MMA_BF16(S[nt][0], S[nt][1], S[nt][2], S[nt][3],
                             qh[ks][0], qh[ks][1], qh[ks][2], qh[ks][3],
                             kh[nt][0], kh[nt][1]);
                    MMA_BF16(S[nt][0], S[nt][1], S[nt][2], S[nt][3],
                             qh[ks][0], qh[ks][1], qh[ks][2], qh[ks][3],
                             kl[nt][0], kl[nt][1]);
                    MMA_BF16(S[nt][0], S[nt][1], S[nt][2], S[nt][3],
                             ql[ks][0], ql[ks][1], ql[ks][2], ql[ks][3],
                             kh[nt][0], kh[nt][1]);
                }
            }
            float mx0 = mr0, mx1 = mr1;
            const int jc = j0 + 2 * (lane & 3);
#pragma unroll
            for (int nt = 0; nt < 8; nt++) {
#pragma unroll
                for (int q = 0; q < 4; q++) {
                    const int jg  = jc + nt * 8 + (q & 1);
                    const int row = (q < 2) ? gqa : gqa + 8;
                    const bool ok = (jg <= row) && (jg < SLEN);
                    const float sv = ok ? S[nt][q] * 0.125f : -1e30f;
                    S[nt][q] = sv;
                    if (q < 2) mx0 = fmaxf(mx0, sv); else mx1 = fmaxf(mx1, sv);
                }
            }
            mx0 = fmaxf(mx0, __shfl_xor_sync(0xffffffffu, mx0, 1));
            mx0 = fmaxf(mx0, __shfl_xor_sync(0xffffffffu, mx0, 2));
            mx1 = fmaxf(mx1, __shfl_xor_sync(0xffffffffu, mx1, 1));
            mx1 = fmaxf(mx1, __shfl_xor_sync(0xffffffffu, mx1, 2));
            const float corr0 = __expf(mr0 - mx0);
            const float corr1 = __expf(mr1 - mx1);
            mr0 = mx0; mr1 = mx1;
            float ps0 = 0.f, ps1 = 0.f;
#pragma unroll
            for (int nt = 0; nt < 8; nt++) {
#pragma unroll
                for (int q = 0; q < 4; q++) {
                    const float p = __expf(S[nt][q] - ((q < 2) ? mx0 : mx1));
                    S[nt][q] = p;
                    if (q < 2) ps0 += p; else ps1 += p;
                }
            }
            ps0 += __shfl_xor_sync(0xffffffffu, ps0, 1);
            ps0 += __shfl_xor_sync(0xffffffffu, ps0, 2);
            ps1 += __shfl_xor_sync(0xffffffffu, ps1, 1);
            ps1 += __shfl_xor_sync(0xffffffffu, ps1, 2);
            l0 = l0 * corr0 + ps0;
            l1 = l1 * corr1 + ps1;
#pragma unroll
            for (int nt = 0; nt < 8; nt++) {
                oacc[nt][0] *= corr0; oacc[nt][1] *= corr0;
                oacc[nt][2] *= corr1; oacc[nt][3] *= corr1;
            }
#pragma unroll
            for (int ks2 = 0; ks2 < 4; ks2++) {
                uint32_t a0, a1, a2, a3;
                PACK_H2(a0, S[2 * ks2][0],     S[2 * ks2][1]);
                PACK_H2(a1, S[2 * ks2][2],     S[2 * ks2][3]);
                PACK_H2(a2, S[2 * ks2 + 1][0], S[2 * ks2 + 1][1]);
                PACK_H2(a3, S[2 * ks2 + 1][2], S[2 * ks2 + 1][3]);
#pragma unroll
                for (int dp = 0; dp < 4; dp++) {
                    uint32_t v0, v1, v2, v3;
                    const uint32_t off =
                        (uint32_t)((ks2 * 16 + vRow) * APAD + dp * 16 + vCof) * 2;
                    LDSM_X4_T(v0, v1, v2, v3, uV + off);
                    MMA_F16(oacc[2 * dp][0], oacc[2 * dp][1],
                            oacc[2 * dp][2], oacc[2 * dp][3],
                            a0, a1, a2, a3, v0, v1);
                    MMA_F16(oacc[2 * dp + 1][0], oacc[2 * dp + 1][1],
                            oacc[2 * dp + 1][2], oacc[2 * dp + 1][3],
                            a0, a1, a2, a3, v2, v3);
                }
            }
        }
        __syncthreads();
    }
#undef FA_ISSUE

    const float inv0 = (l0 > 0.f) ? 1.f / l0 : 0.f;
    const float inv1 = (l1 > 0.f) ? 1.f / l1 : 0.f;
#pragma unroll
    for (int nt = 0; nt < 8; nt++) {
        const int d = colOff + nt * 8 + 2 * (lane & 3);
        if (gqa < SLEN) {
            __half2 hv = {__float2half_rn(oacc[nt][0] * inv0),
                          __float2half_rn(oacc[nt][1] * inv0)};
            *(__half2*)(Oh + (rowBase + gqa) * NSTATE + d) = hv;
        }
        if (gqa + 8 < SLEN) {
            __half2 hv = {__float2half_rn(oacc[nt][2] * inv1),
                          __float2half_rn(oacc[nt][3] * inv1)};
            *(__half2*)(Oh + (rowBase + gqa + 8) * NSTATE + d) = hv;
        }
    }
}

// ---------------- launch -----------------------------------------------------
extern "C" void kernel_launch(void* const* d_in, const int* in_sizes, int n_in,
                              void* d_out, int out_size)
{
    const float* x  = (const float*)d_in[0];
    const float* Wq = (const float*)d_in[2];
    const float* bq = (const float*)d_in[3];
    const float* Wk = (const float*)d_in[4];
    const float* Wv = (const float*)d_in[5];
    const float* bv = (const float*)d_in[6];
    const float* Wo = (const float*)d_in[7];
    const float* bo = (const float*)d_in[8];
    float* out = (float*)d_out;

    __nv_bfloat16 *xhi, *xlo, *qhi, *qlo, *khi, *klo, *whi, *wlo;
    __half *xh, *vh, *oh, *wvh, *woh;
    cudaGetSymbolAddress((void**)&xhi, g_Xhi);
    cudaGetSymbolAddress((void**)&xlo, g_Xlo);
    cudaGetSymbolAddress((void**)&xh,  g_Xh);
    cudaGetSymbolAddress((void**)&qhi, g_Qhi);
    cudaGetSymbolAddress((void**)&qlo, g_Qlo);
    cudaGetSymbolAddress((void**)&khi, g_Khi);
    cudaGetSymbolAddress((void**)&klo, g_Klo);
    cudaGetSymbolAddress((void**)&vh,  g_Vh);
    cudaGetSymbolAddress((void**)&oh,  g_Oh);
    cudaGetSymbolAddress((void**)&whi, g_Whi);
    cudaGetSymbolAddress((void**)&wlo, g_Wlo);
    cudaGetSymbolAddress((void**)&wvh, g_Wvh);
    cudaGetSymbolAddress((void**)&woh, g_Woh);
    const size_t WSZ = (size_t)NSTATE * NSTATE;

    cudaFuncSetAttribute(gemm_qk_kernel,
                         cudaFuncAttributeMaxDynamicSharedMemorySize, GSMEM4);
    cudaFuncSetAttribute(gemm_f16_kernel<0>,
                         cudaFuncAttributeMaxDynamicSharedMemorySize, GSMEM2);
    cudaFuncSetAttribute(gemm_f16_kernel<1>,
                         cudaFuncAttributeMaxDynamicSharedMemorySize, GSMEM2);
    cudaFuncSetAttribute(flash_hmma_kernel,
                         cudaFuncAttributeMaxDynamicSharedMemorySize, FSMEM);

    const int xn4 = MROWS * NSTATE / 4;
    const int wn4 = NSTATE * NSTATE / 4;
    // x -> bf16 hi/lo (for Q,K projections)
    split_bf16_kernel<<<dim3((xn4 + 255) / 256, 1), 256>>>(
        x, nullptr, nullptr, xhi, xlo, 0, xn4);
    // Wq, Wk -> bf16 hi/lo
    split_bf16_kernel<<<dim3((wn4 + 255) / 256, 2), 256>>>(
        Wq, Wk, nullptr, whi, wlo, WSZ, wn4);
    // x -> fp16 (for V projection)
    cvt_f16_kernel<<<dim3((xn4 + 255) / 256, 1), 256>>>(
        x, nullptr, xh, nullptr, xn4);
    // Wv, Wo -> fp16
    cvt_f16_kernel<<<dim3((wn4 + 255) / 256, 2), 256>>>(
        Wv, Wo, wvh, woh, wn4);

    // Q and K projections (split-bf16, fused z=2)
    const dim3 qkgrid(NSTATE / 128, (MROWS + 127) / 128, 2);
    gemm_qk_kernel<<<qkgrid, 256, GSMEM4>>>(
        xhi, xlo, whi, wlo, bq, qhi, qlo, khi, klo, MROWS);

    // V projection (fp16, single MMA)
    const dim3 vgrid(NSTATE / 128, (MROWS + 127) / 128, 1);
    gemm_f16_kernel<0><<<vgrid, 256, GSMEM2>>>(xh, wvh, bv, vh, nullptr, MROWS);

    const dim3 agrid((SLEN + AQ - 1) / AQ, BATCH * NHEAD);
    flash_hmma_kernel<<<agrid, 256, FSMEM>>>(qhi, qlo, khi, klo, vh, oh);

    // O projection (fp16, single MMA) -> fp32 out
    gemm_f16_kernel<1><<<vgrid, 256, GSMEM2>>>(oh, woh, bo, nullptr, out, MROWS);
}

// round 9
// speedup vs baseline: 2.1725x; 1.5992x over previous
#include <cuda_runtime.h>
#include <cuda_bf16.h>
#include <cuda_fp16.h>
#include <cstdint>

#define BATCH  8
#define SLEN   1500
#define NSTATE 1024
#define NHEAD  16
#define HDIM   64
#define MROWS  (BATCH * SLEN)   // 12000

// ---------------- scratch (static device globals; no allocation) -------------
__device__ __half g_Xh[(size_t)MROWS * NSTATE];
__device__ __half g_Qh[(size_t)MROWS * NSTATE];
__device__ __half g_Kh[(size_t)MROWS * NSTATE];
__device__ __half g_Vh[(size_t)MROWS * NSTATE];
__device__ __half g_Oh[(size_t)MROWS * NSTATE];
__device__ __half g_Wh[4][(size_t)NSTATE * NSTATE];

__device__ __forceinline__ uint32_t smem_u32(const void* p) {
    uint32_t a;
    asm("{ .reg .u64 t; cvta.to.shared.u64 t, %1; cvt.u32.u64 %0, t; }"
        : "=r"(a) : "l"(p));
    return a;
}

#define LDSM_X4(r0, r1, r2, r3, addr)                                            \
    asm volatile("ldmatrix.sync.aligned.m8n8.x4.shared.b16 {%0,%1,%2,%3}, [%4];" \
                 : "=r"(r0), "=r"(r1), "=r"(r2), "=r"(r3) : "r"(addr))

#define LDSM_X4_T(r0, r1, r2, r3, addr)                                          \
    asm volatile("ldmatrix.sync.aligned.m8n8.x4.trans.shared.b16 {%0,%1,%2,%3}, [%4];" \
                 : "=r"(r0), "=r"(r1), "=r"(r2), "=r"(r3) : "r"(addr))

#define MMA_F16(c0, c1, c2, c3, a0, a1, a2, a3, b0, b1)                          \
    asm volatile("mma.sync.aligned.m16n8k16.row.col.f32.f16.f16.f32 "            \
                 "{%0,%1,%2,%3}, {%4,%5,%6,%7}, {%8,%9}, {%0,%1,%2,%3};"         \
                 : "+f"(c0), "+f"(c1), "+f"(c2), "+f"(c3)                        \
                 : "r"(a0), "r"(a1), "r"(a2), "r"(a3), "r"(b0), "r"(b1))

#define PACK_H2(d, vlo, vhi)                                                     \
    asm("cvt.rn.f16x2.f32 %0, %1, %2;" : "=r"(d) : "f"(vhi), "f"(vlo))

#define CP16(dst, src, nbytes)                                                   \
    asm volatile("cp.async.cg.shared.global [%0], [%1], 16, %2;"                 \
                 :: "r"(dst), "l"(src), "r"(nbytes))
#define CP_COMMIT() asm volatile("cp.async.commit_group;" ::: "memory")
#define CP_WAIT1()  asm volatile("cp.async.wait_group 1;" ::: "memory")
#define CP_WAIT0()  asm volatile("cp.async.wait_group 0;" ::: "memory")

// ======================= convert fp32 -> fp16 ================================
__global__ __launch_bounds__(256) void cvt_f16_kernel(
    const float* __restrict__ in0, const float* __restrict__ in1,
    const float* __restrict__ in2, const float* __restrict__ in3,
    __half* __restrict__ o, size_t zstride, int n4)
{
    const int z = blockIdx.y;
    const float* in = (z == 0) ? in0 : (z == 1) ? in1 : (z == 2) ? in2 : in3;
    o += z * zstride;
    int i = blockIdx.x * blockDim.x + threadIdx.x;
    if (i < n4) {
        float4 v = *(const float4*)(in + (size_t)i * 4);
        __half2 h0 = {__float2half_rn(v.x), __float2half_rn(v.y)};
        __half2 h1 = {__float2half_rn(v.z), __float2half_rn(v.w)};
        *(__half2*)(o + (size_t)i * 4)     = h0;
        *(__half2*)(o + (size_t)i * 4 + 2) = h1;
    }
}

// ===== fp16 single-MMA GEMM (2-stage cp.async) ===============================
// PASS 0: grid.z z in {0:Q(+bq), 1:K, 2:V(+bv)} -> fp16 outs
// PASS 1: O gemm -> fp32 out (+bo)
#define GBK     32
#define GPAD    40
#define GK_ITERS (NSTATE / GBK)            // 32
#define ARR_B   (128 * GPAD * 2)           // 10240 bytes per array
#define STG2_B  (2 * ARR_B)                // 20480 bytes per stage
#define GSMEM2  (2 * STG2_B)               // 40960 bytes

template <int PASS>
__global__ __launch_bounds__(256) void gemm_f16_kernel(
    const __half* __restrict__ A, const __half* __restrict__ W,
    const float* __restrict__ bq, const float* __restrict__ bv,
    const float* __restrict__ bo,
    __half* __restrict__ outQ, __half* __restrict__ outK,
    __half* __restrict__ outV, float* __restrict__ outF, int M)
{
    extern __shared__ __align__(16) char dsm[];
    const int z = (PASS == 0) ? blockIdx.z : 3;
    const __half* B = W + (size_t)z * NSTATE * NSTATE;
    const float* bias = (PASS == 1) ? bo : ((z == 0) ? bq : (z == 2) ? bv : nullptr);

    const int tid  = threadIdx.x;
    const int wid  = tid >> 5;
    const int lane = tid & 31;
    const int m0 = blockIdx.y * 128;
    const int n0 = blockIdx.x * 128;
    const int mbase = (wid >> 2) * 64;
    const int nbase = (wid & 3) * 32;
    const uint32_t uBase = smem_u32(dsm);

    float acc[4][4][4];
#pragma unroll
    for (int i = 0; i < 4; i++)
#pragma unroll
        for (int j = 0; j < 4; j++)
#pragma unroll
            for (int q = 0; q < 4; q++) acc[i][j][q] = 0.f;

    const int lrow0 = (tid + 0)   >> 2, lc0 = (tid & 3) * 8;
    const int lrow1 = (tid + 256) >> 2;
    const int okA0 = (m0 + lrow0 < M) ? 16 : 0;
    const int okA1 = (m0 + lrow1 < M) ? 16 : 0;
    const size_t ga0 = (size_t)(m0 + lrow0) * NSTATE + lc0;
    const size_t ga1 = (size_t)(m0 + lrow1) * NSTATE + lc0;
    const size_t gb0 = (size_t)(n0 + lrow0) * NSTATE + lc0;
    const size_t gb1 = (size_t)(n0 + lrow1) * NSTATE + lc0;
    const uint32_t so0 = (uint32_t)(lrow0 * GPAD + lc0) * 2;
    const uint32_t so1 = (uint32_t)(lrow1 * GPAD + lc0) * 2;

#define ISSUE2(kit, stg) do {                                                    \
        const int k0_ = (kit) * GBK;                                             \
        const uint32_t sb = uBase + (stg) * STG2_B;                              \
        CP16(sb + 0 * ARR_B + so0, A + ga0 + k0_, okA0);                         \
        CP16(sb + 0 * ARR_B + so1, A + ga1 + k0_, okA1);                         \
        CP16(sb + 1 * ARR_B + so0, B + gb0 + k0_, 16);                           \
        CP16(sb + 1 * ARR_B + so1, B + gb1 + k0_, 16);                           \
        CP_COMMIT();                                                             \
    } while (0)

    ISSUE2(0, 0);

    const int aRow = lane & 15, aKof = (lane >> 4) * 8;
    const int bNof = ((lane >> 4) * 8) + (lane & 7);
    const int bKof = ((lane >> 3) & 1) * 8;

    for (int kit = 0; kit < GK_ITERS; kit++) {
        if (kit + 1 < GK_ITERS) { ISSUE2(kit + 1, (kit + 1) & 1); CP_WAIT1(); }
        else                    { CP_WAIT0(); }
        __syncthreads();

        const uint32_t sb = uBase + (kit & 1) * STG2_B;
        const uint32_t uA = sb, uB = sb + ARR_B;
#pragma unroll
        for (int ks = 0; ks < 2; ks++) {
            const int kof = ks * 16;
            uint32_t a[4][4];
#pragma unroll
            for (int mt = 0; mt < 4; mt++) {
                const uint32_t off =
                    (uint32_t)((mbase + mt * 16 + aRow) * GPAD + kof + aKof) * 2;
                LDSM_X4(a[mt][0], a[mt][1], a[mt][2], a[mt][3], uA + off);
            }
            uint32_t b[4][2];
#pragma unroll
            for (int np = 0; np < 2; np++) {
                const uint32_t off =
                    (uint32_t)((nbase + np * 16 + bNof) * GPAD + kof + bKof) * 2;
                LDSM_X4(b[np * 2][0], b[np * 2][1], b[np * 2 + 1][0], b[np * 2 + 1][1],
                        uB + off);
            }
#pragma unroll
            for (int mt = 0; mt < 4; mt++)
#pragma unroll
                for (int nt = 0; nt < 4; nt++) {
                    float* c4 = acc[mt][nt];
                    MMA_F16(c4[0], c4[1], c4[2], c4[3],
                            a[mt][0], a[mt][1], a[mt][2], a[mt][3],
                            b[nt][0], b[nt][1]);
                }
        }
        __syncthreads();
    }
#undef ISSUE2

    const int lr = lane >> 2;
    const int lc = (lane & 3) * 2;
#pragma unroll
    for (int mt = 0; mt < 4; mt++) {
#pragma unroll
        for (int half_ = 0; half_ < 2; half_++) {
            const int gm = m0 + mbase + mt * 16 + half_ * 8 + lr;
            if (gm < M) {
#pragma unroll
                for (int nt = 0; nt < 4; nt++) {
                    const int gn = n0 + nbase + nt * 8 + lc;
                    float vx = acc[mt][nt][half_ * 2 + 0];
                    float vy = acc[mt][nt][half_ * 2 + 1];
                    if (bias) { vx += bias[gn]; vy += bias[gn + 1]; }
                    const size_t idx = (size_t)gm * NSTATE + gn;
                    if (PASS == 1) {
                        *(float2*)(outF + idx) = make_float2(vx, vy);
                    } else {
                        __half2 hv = {__float2half_rn(vx), __float2half_rn(vy)};
                        __half* o = (z == 0) ? outQ : (z == 1) ? outK : outV;
                        *(__half2*)(o + idx) = hv;
                    }
                }
            }
        }
    }
}

// ================= fp16 HMMA flash attention (causal, cp.async 2-stage) ======
#define AQ    128
#define AKV   64
#define APAD  72
#define FARR  (AKV * APAD * 2)     // 9216 bytes per K/V array
#define FSTG  (2 * FARR)           // 18432 bytes per stage (K, V)
#define FSMEM (2 * FSTG)           // 36864 bytes

__global__ __launch_bounds__(256, 2) void flash_hmma_kernel(
    const __half* __restrict__ Qh, const __half* __restrict__ Kh,
    const __half* __restrict__ Vh, __half* __restrict__ Oh)
{
    extern __shared__ __align__(16) char fsm[];
    const uint32_t uS = smem_u32(fsm);

    const int tid  = threadIdx.x;
    const int wid  = tid >> 5;
    const int lane = tid & 31;
    const int bh = blockIdx.y;
    const int b  = bh >> 4;
    const int h  = bh & 15;
    // longest (highest q0) CTAs first
    const int q0 = (gridDim.x - 1 - blockIdx.x) * AQ;
    const size_t rowBase = (size_t)b * SLEN;
    const int colOff = h * HDIM;

    // ---- stage Q (128x64 fp16) into fsm[0:18432) ----
#pragma unroll
    for (int it = 0; it < 4; it++) {
        const int id = tid + it * 256;
        const int r  = id >> 3;
        const int c  = id & 7;
        const int gq = q0 + r;
        uint4 v = make_uint4(0, 0, 0, 0);
        if (gq < SLEN)
            v = *(const uint4*)(Qh + (rowBase + gq) * NSTATE + colOff + c * 8);
        *(uint4*)(fsm + (r * APAD + c * 8) * 2) = v;
    }
    __syncthreads();

    const int aRow = lane & 15, aKof = (lane >> 4) * 8;
    const int wq0 = wid * 16;
    uint32_t qf[4][4];
#pragma unroll
    for (int ks = 0; ks < 4; ks++) {
        const uint32_t off = (uint32_t)((wq0 + aRow) * APAD + ks * 16 + aKof) * 2;
        LDSM_X4(qf[ks][0], qf[ks][1], qf[ks][2], qf[ks][3], uS + off);
    }
    __syncthreads();

#define FA_ISSUE(t, stg) do {                                                    \
        const int j0_ = (t) * AKV;                                               \
        const uint32_t sb = uS + (stg) * FSTG;                                   \
        _Pragma("unroll")                                                        \
        for (int it = 0; it < 2; it++) {                                         \
            const int id = tid + it * 256;                                       \
            const int r  = id >> 3;                                              \
            const int c  = id & 7;                                               \
            const int gk = j0_ + r;                                              \
            const int nb = (gk < SLEN) ? 16 : 0;                                 \
            const size_t off = (rowBase + gk) * NSTATE + colOff + c * 8;         \
            const uint32_t so = (uint32_t)(r * APAD + c * 8) * 2;                \
            CP16(sb + 0 * FARR + so, Kh + off, nb);                              \
            CP16(sb + 1 * FARR + so, Vh + off, nb);                              \
        }                                                                        \
        CP_COMMIT();                                                             \
    } while (0)

    const int gqa = q0 + wq0 + (lane >> 2);
    float mr0 = -1e30f, mr1 = -1e30f, l0 = 0.f, l1 = 0.f;
    float oacc[8][4];
#pragma unroll
    for (int i = 0; i < 8; i++)
#pragma unroll
        for (int q = 0; q < 4; q++) oacc[i][q] = 0.f;

    const int bNof = ((lane >> 4) * 8) + (lane & 7);
    const int bKof = ((lane >> 3) & 1) * 8;
    const int vRow = ((lane >> 3) & 1) * 8 + (lane & 7);
    const int vCof = (lane >> 4) * 8;

    const int tEnd = min(q0 + AQ - 1, SLEN - 1) / AKV;
    FA_ISSUE(0, 0);

    for (int t = 0; t <= tEnd; t++) {
        const int j0 = t * AKV;
        if (t + 1 <= tEnd) { FA_ISSUE(t + 1, (t + 1) & 1); CP_WAIT1(); }
        else               { CP_WAIT0(); }
        __syncthreads();

        const uint32_t sb = uS + (t & 1) * FSTG;
        const uint32_t uK = sb, uV = sb + FARR;

        if (j0 <= q0 + wq0 + 15) {
            // ---- S = Q K^T (fp16, single MMA) ----
            float S[8][4];
#pragma unroll
            for (int nt = 0; nt < 8; nt++)
#pragma unroll
                for (int q = 0; q < 4; q++) S[nt][q] = 0.f;
#pragma unroll
            for (int ks = 0; ks < 4; ks++) {
                uint32_t kf[8][2];
#pragma unroll
                for (int np = 0; np < 4; np++) {
                    const uint32_t off =
                        (uint32_t)((np * 16 + bNof) * APAD + ks * 16 + bKof) * 2;
                    LDSM_X4(kf[np * 2][0], kf[np * 2][1],
                            kf[np * 2 + 1][0], kf[np * 2 + 1][1], uK + off);
                }
#pragma unroll
                for (int nt = 0; nt < 8; nt++)
                    MMA_F16(S[nt][0], S[nt][1], S[nt][2], S[nt][3],
                            qf[ks][0], qf[ks][1], qf[ks][2], qf[ks][3],
                            kf[nt][0], kf[nt][1]);
            }
            // ---- masked online softmax ----
            float mx0 = mr0, mx1 = mr1;
            const int jc = j0 + 2 * (lane & 3);
#pragma unroll
            for (int nt = 0; nt < 8; nt++) {
#pragma unroll
                for (int q = 0; q < 4; q++) {
                    const int jg  = jc + nt * 8 + (q & 1);
                    const int row = (q < 2) ? gqa : gqa + 8;
                    const bool ok = (jg <= row) && (jg < SLEN);
                    const float sv = ok ? S[nt][q] * 0.125f : -1e30f;
                    S[nt][q] = sv;
                    if (q < 2) mx0 = fmaxf(mx0, sv); else mx1 = fmaxf(mx1, sv);
                }
            }
            mx0 = fmaxf(mx0, __shfl_xor_sync(0xffffffffu, mx0, 1));
            mx0 = fmaxf(mx0, __shfl_xor_sync(0xffffffffu, mx0, 2));
            mx1 = fmaxf(mx1, __shfl_xor_sync(0xffffffffu, mx1, 1));
            mx1 = fmaxf(mx1, __shfl_xor_sync(0xffffffffu, mx1, 2));
            const float corr0 = __expf(mr0 - mx0);
            const float corr1 = __expf(mr1 - mx1);
            mr0 = mx0; mr1 = mx1;
            float ps0 = 0.f, ps1 = 0.f;
#pragma unroll
            for (int nt = 0; nt < 8; nt++) {
#pragma unroll
                for (int q = 0; q < 4; q++) {
                    const float p = __expf(S[nt][q] - ((q < 2) ? mx0 : mx1));
                    S[nt][q] = p;
                    if (q < 2) ps0 += p; else ps1 += p;
                }
            }
            ps0 += __shfl_xor_sync(0xffffffffu, ps0, 1);
            ps0 += __shfl_xor_sync(0xffffffffu, ps0, 2);
            ps1 += __shfl_xor_sync(0xffffffffu, ps1, 1);
            ps1 += __shfl_xor_sync(0xffffffffu, ps1, 2);
            l0 = l0 * corr0 + ps0;
            l1 = l1 * corr1 + ps1;
#pragma unroll
            for (int nt = 0; nt < 8; nt++) {
                oacc[nt][0] *= corr0; oacc[nt][1] *= corr0;
                oacc[nt][2] *= corr1; oacc[nt][3] *= corr1;
            }
            // ---- O += P V (fp16) ----
#pragma unroll
            for (int ks2 = 0; ks2 < 4; ks2++) {
                uint32_t a0, a1, a2, a3;
                PACK_H2(a0, S[2 * ks2][0],     S[2 * ks2][1]);
                PACK_H2(a1, S[2 * ks2][2],     S[2 * ks2][3]);
                PACK_H2(a2, S[2 * ks2 + 1][0], S[2 * ks2 + 1][1]);
                PACK_H2(a3, S[2 * ks2 + 1][2], S[2 * ks2 + 1][3]);
#pragma unroll
                for (int dp = 0; dp < 4; dp++) {
                    uint32_t v0, v1, v2, v3;
                    const uint32_t off =
                        (uint32_t)((ks2 * 16 + vRow) * APAD + dp * 16 + vCof) * 2;
                    LDSM_X4_T(v0, v1, v2, v3, uV + off);
                    MMA_F16(oacc[2 * dp][0], oacc[2 * dp][1],
                            oacc[2 * dp][2], oacc[2 * dp][3],
                            a0, a1, a2, a3, v0, v1);
                    MMA_F16(oacc[2 * dp + 1][0], oacc[2 * dp + 1][1],
                            oacc[2 * dp + 1][2], oacc[2 * dp + 1][3],
                            a0, a1, a2, a3, v2, v3);
                }
            }
        }
        __syncthreads();
    }
#undef FA_ISSUE

    const float inv0 = (l0 > 0.f) ? 1.f / l0 : 0.f;
    const float inv1 = (l1 > 0.f) ? 1.f / l1 : 0.f;
#pragma unroll
    for (int nt = 0; nt < 8; nt++) {
        const int d = colOff + nt * 8 + 2 * (lane & 3);
        if (gqa < SLEN) {
            __half2 hv = {__float2half_rn(oacc[nt][0] * inv0),
                          __float2half_rn(oacc[nt][1] * inv0)};
            *(__half2*)(Oh + (rowBase + gqa) * NSTATE + d) = hv;
        }
        if (gqa + 8 < SLEN) {
            __half2 hv = {__float2half_rn(oacc[nt][2] * inv1),
                          __float2half_rn(oacc[nt][3] * inv1)};
            *(__half2*)(Oh + (rowBase + gqa + 8) * NSTATE + d) = hv;
        }
    }
}

// ---------------- launch -----------------------------------------------------
extern "C" void kernel_launch(void* const* d_in, const int* in_sizes, int n_in,
                              void* d_out, int out_size)
{
    const float* x  = (const float*)d_in[0];
    const float* Wq = (const float*)d_in[2];
    const float* bq = (const float*)d_in[3];
    const float* Wk = (const float*)d_in[4];
    const float* Wv = (const float*)d_in[5];
    const float* bv = (const float*)d_in[6];
    const float* Wo = (const float*)d_in[7];
    const float* bo = (const float*)d_in[8];
    float* out = (float*)d_out;

    __half *xh, *qh, *kh, *vh, *oh, *wh;
    cudaGetSymbolAddress((void**)&xh, g_Xh);
    cudaGetSymbolAddress((void**)&qh, g_Qh);
    cudaGetSymbolAddress((void**)&kh, g_Kh);
    cudaGetSymbolAddress((void**)&vh, g_Vh);
    cudaGetSymbolAddress((void**)&oh, g_Oh);
    cudaGetSymbolAddress((void**)&wh, g_Wh);
    const size_t WSZ = (size_t)NSTATE * NSTATE;

    cudaFuncSetAttribute(gemm_f16_kernel<0>,
                         cudaFuncAttributeMaxDynamicSharedMemorySize, GSMEM2);
    cudaFuncSetAttribute(gemm_f16_kernel<1>,
                         cudaFuncAttributeMaxDynamicSharedMemorySize, GSMEM2);
    cudaFuncSetAttribute(flash_hmma_kernel,
                         cudaFuncAttributeMaxDynamicSharedMemorySize, FSMEM);

    const int xn4 = MROWS * NSTATE / 4;
    const int wn4 = NSTATE * NSTATE / 4;
    // x -> fp16
    cvt_f16_kernel<<<dim3((xn4 + 255) / 256, 1), 256>>>(
        x, nullptr, nullptr, nullptr, xh, 0, xn4);
    // Wq, Wk, Wv, Wo -> fp16 (one launch)
    cvt_f16_kernel<<<dim3((wn4 + 255) / 256, 4), 256>>>(
        Wq, Wk, Wv, Wo, wh, WSZ, wn4);

    // fused Q/K/V projections (fp16 single-MMA)
    const dim3 qkvgrid(NSTATE / 128, (MROWS + 127) / 128, 3);
    gemm_f16_kernel<0><<<qkvgrid, 256, GSMEM2>>>(
        xh, wh, bq, bv, bo, qh, kh, vh, nullptr, MROWS);

    const dim3 agrid((SLEN + AQ - 1) / AQ, BATCH * NHEAD);
    flash_hmma_kernel<<<agrid, 256, FSMEM>>>(qh, kh, vh, oh);

    // O projection -> fp32 out
    const dim3 ogrid(NSTATE / 128, (MROWS + 127) / 128, 1);
    gemm_f16_kernel<1><<<ogrid, 256, GSMEM2>>>(
        oh, wh, bq, bv, bo, nullptr, nullptr, nullptr, out, MROWS);
}

// round 10
// speedup vs baseline: 2.3026x; 1.0599x over previous
#include <cuda_runtime.h>
#include <cuda_bf16.h>
#include <cuda_fp16.h>
#include <cstdint>

#define BATCH  8
#define SLEN   1500
#define NSTATE 1024
#define NHEAD  16
#define HDIM   64
#define MROWS  (BATCH * SLEN)   // 12000

// scale folded into Q projection: 1/sqrt(64) * log2(e)
#define QSCALE 0.18033688011112042f

// ---------------- scratch (static device globals; no allocation) -------------
__device__ __half g_Xh[(size_t)MROWS * NSTATE];
__device__ __half g_Qh[(size_t)MROWS * NSTATE];
__device__ __half g_Kh[(size_t)MROWS * NSTATE];
__device__ __half g_Vh[(size_t)MROWS * NSTATE];
__device__ __half g_Oh[(size_t)MROWS * NSTATE];
__device__ __half g_Wh[4][(size_t)NSTATE * NSTATE];

__device__ __forceinline__ uint32_t smem_u32(const void* p) {
    uint32_t a;
    asm("{ .reg .u64 t; cvta.to.shared.u64 t, %1; cvt.u32.u64 %0, t; }"
        : "=r"(a) : "l"(p));
    return a;
}
__device__ __forceinline__ float ex2f(float x) {
    float r;
    asm("ex2.approx.f32 %0, %1;" : "=f"(r) : "f"(x));
    return r;
}

#define LDSM_X4(r0, r1, r2, r3, addr)                                            \
    asm volatile("ldmatrix.sync.aligned.m8n8.x4.shared.b16 {%0,%1,%2,%3}, [%4];" \
                 : "=r"(r0), "=r"(r1), "=r"(r2), "=r"(r3) : "r"(addr))

#define LDSM_X4_T(r0, r1, r2, r3, addr)                                          \
    asm volatile("ldmatrix.sync.aligned.m8n8.x4.trans.shared.b16 {%0,%1,%2,%3}, [%4];" \
                 : "=r"(r0), "=r"(r1), "=r"(r2), "=r"(r3) : "r"(addr))

#define MMA_F16(c0, c1, c2, c3, a0, a1, a2, a3, b0, b1)                          \
    asm volatile("mma.sync.aligned.m16n8k16.row.col.f32.f16.f16.f32 "            \
                 "{%0,%1,%2,%3}, {%4,%5,%6,%7}, {%8,%9}, {%0,%1,%2,%3};"         \
                 : "+f"(c0), "+f"(c1), "+f"(c2), "+f"(c3)                        \
                 : "r"(a0), "r"(a1), "r"(a2), "r"(a3), "r"(b0), "r"(b1))

#define PACK_H2(d, vlo, vhi)                                                     \
    asm("cvt.rn.f16x2.f32 %0, %1, %2;" : "=r"(d) : "f"(vhi), "f"(vlo))

#define CP16(dst, src, nbytes)                                                   \
    asm volatile("cp.async.cg.shared.global [%0], [%1], 16, %2;"                 \
                 :: "r"(dst), "l"(src), "r"(nbytes))
#define CP_COMMIT() asm volatile("cp.async.commit_group;" ::: "memory")
#define CP_WAIT2()  asm volatile("cp.async.wait_group 2;" ::: "memory")
#define CP_WAIT1()  asm volatile("cp.async.wait_group 1;" ::: "memory")
#define CP_WAIT0()  asm volatile("cp.async.wait_group 0;" ::: "memory")

// ======================= convert fp32 -> fp16 ================================
__global__ __launch_bounds__(256) void cvt_f16_kernel(
    const float* __restrict__ in0, const float* __restrict__ in1,
    const float* __restrict__ in2, const float* __restrict__ in3,
    __half* __restrict__ o, size_t zstride, int n4)
{
    const int z = blockIdx.y;
    const float* in = (z == 0) ? in0 : (z == 1) ? in1 : (z == 2) ? in2 : in3;
    o += z * zstride;
    int i = blockIdx.x * blockDim.x + threadIdx.x;
    if (i < n4) {
        float4 v = *(const float4*)(in + (size_t)i * 4);
        __half2 h0 = {__float2half_rn(v.x), __float2half_rn(v.y)};
        __half2 h1 = {__float2half_rn(v.z), __float2half_rn(v.w)};
        *(__half2*)(o + (size_t)i * 4)     = h0;
        *(__half2*)(o + (size_t)i * 4 + 2) = h1;
    }
}

// ===== fp16 single-MMA GEMM (3-stage cp.async) ===============================
// PASS 0: grid.z z in {0:Q(+bq, *QSCALE), 1:K, 2:V(+bv)} -> fp16 outs
// PASS 1: O gemm -> fp32 out (+bo)
#define GBK     32
#define GPAD    40
#define GK_ITERS (NSTATE / GBK)            // 32
#define ARR_B   (128 * GPAD * 2)           // 10240 bytes per array
#define STG2_B  (2 * ARR_B)                // 20480 bytes per stage
#define GSTAGES 3
#define GSMEM2  (GSTAGES * STG2_B)         // 61440 bytes

template <int PASS>
__global__ __launch_bounds__(256) void gemm_f16_kernel(
    const __half* __restrict__ A, const __half* __restrict__ W,
    const float* __restrict__ bq, const float* __restrict__ bv,
    const float* __restrict__ bo,
    __half* __restrict__ outQ, __half* __restrict__ outK,
    __half* __restrict__ outV, float* __restrict__ outF, int M)
{
    extern __shared__ __align__(16) char dsm[];
    const int z = (PASS == 0) ? blockIdx.z : 3;
    const __half* B = W + (size_t)z * NSTATE * NSTATE;
    const float* bias = (PASS == 1) ? bo : ((z == 0) ? bq : (z == 2) ? bv : nullptr);

    const int tid  = threadIdx.x;
    const int wid  = tid >> 5;
    const int lane = tid & 31;
    const int m0 = blockIdx.y * 128;
    const int n0 = blockIdx.x * 128;
    const int mbase = (wid >> 2) * 64;
    const int nbase = (wid & 3) * 32;
    const uint32_t uBase = smem_u32(dsm);

    float acc[4][4][4];
#pragma unroll
    for (int i = 0; i < 4; i++)
#pragma unroll
        for (int j = 0; j < 4; j++)
#pragma unroll
            for (int q = 0; q < 4; q++) acc[i][j][q] = 0.f;

    const int lrow0 = (tid + 0)   >> 2, lc0 = (tid & 3) * 8;
    const int lrow1 = (tid + 256) >> 2;
    const int okA0 = (m0 + lrow0 < M) ? 16 : 0;
    const int okA1 = (m0 + lrow1 < M) ? 16 : 0;
    const size_t ga0 = (size_t)(m0 + lrow0) * NSTATE + lc0;
    const size_t ga1 = (size_t)(m0 + lrow1) * NSTATE + lc0;
    const size_t gb0 = (size_t)(n0 + lrow0) * NSTATE + lc0;
    const size_t gb1 = (size_t)(n0 + lrow1) * NSTATE + lc0;
    const uint32_t so0 = (uint32_t)(lrow0 * GPAD + lc0) * 2;
    const uint32_t so1 = (uint32_t)(lrow1 * GPAD + lc0) * 2;

#define ISSUE2(kit, stg) do {                                                    \
        const int k0_ = (kit) * GBK;                                             \
        const uint32_t sb = uBase + (stg) * STG2_B;                              \
        CP16(sb + 0 * ARR_B + so0, A + ga0 + k0_, okA0);                         \
        CP16(sb + 0 * ARR_B + so1, A + ga1 + k0_, okA1);                         \
        CP16(sb + 1 * ARR_B + so0, B + gb0 + k0_, 16);                           \
        CP16(sb + 1 * ARR_B + so1, B + gb1 + k0_, 16);                           \
        CP_COMMIT();                                                             \
    } while (0)

    ISSUE2(0, 0);
    ISSUE2(1, 1);

    const int aRow = lane & 15, aKof = (lane >> 4) * 8;
    const int bNof = ((lane >> 4) * 8) + (lane & 7);
    const int bKof = ((lane >> 3) & 1) * 8;

    for (int kit = 0; kit < GK_ITERS; kit++) {
        if      (kit + 2 < GK_ITERS) { ISSUE2(kit + 2, (kit + 2) % GSTAGES); CP_WAIT2(); }
        else if (kit + 1 < GK_ITERS) { CP_WAIT1(); }
        else                         { CP_WAIT0(); }
        __syncthreads();

        const uint32_t sb = uBase + (kit % GSTAGES) * STG2_B;
        const uint32_t uA = sb, uB = sb + ARR_B;
#pragma unroll
        for (int ks = 0; ks < 2; ks++) {
            const int kof = ks * 16;
            uint32_t a[4][4];
#pragma unroll
            for (int mt = 0; mt < 4; mt++) {
                const uint32_t off =
                    (uint32_t)((mbase + mt * 16 + aRow) * GPAD + kof + aKof) * 2;
                LDSM_X4(a[mt][0], a[mt][1], a[mt][2], a[mt][3], uA + off);
            }
            uint32_t b[4][2];
#pragma unroll
            for (int np = 0; np < 2; np++) {
                const uint32_t off =
                    (uint32_t)((nbase + np * 16 + bNof) * GPAD + kof + bKof) * 2;
                LDSM_X4(b[np * 2][0], b[np * 2][1], b[np * 2 + 1][0], b[np * 2 + 1][1],
                        uB + off);
            }
#pragma unroll
            for (int mt = 0; mt < 4; mt++)
#pragma unroll
                for (int nt = 0; nt < 4; nt++) {
                    float* c4 = acc[mt][nt];
                    MMA_F16(c4[0], c4[1], c4[2], c4[3],
                            a[mt][0], a[mt][1], a[mt][2], a[mt][3],
                            b[nt][0], b[nt][1]);
                }
        }
        __syncthreads();
    }
#undef ISSUE2

    const int lr = lane >> 2;
    const int lc = (lane & 3) * 2;
#pragma unroll
    for (int mt = 0; mt < 4; mt++) {
#pragma unroll
        for (int half_ = 0; half_ < 2; half_++) {
            const int gm = m0 + mbase + mt * 16 + half_ * 8 + lr;
            if (gm < M) {
#pragma unroll
                for (int nt = 0; nt < 4; nt++) {
                    const int gn = n0 + nbase + nt * 8 + lc;
                    float vx = acc[mt][nt][half_ * 2 + 0];
                    float vy = acc[mt][nt][half_ * 2 + 1];
                    if (bias) { vx += bias[gn]; vy += bias[gn + 1]; }
                    if (PASS == 0 && z == 0) { vx *= QSCALE; vy *= QSCALE; }
                    const size_t idx = (size_t)gm * NSTATE + gn;
                    if (PASS == 1) {
                        *(float2*)(outF + idx) = make_float2(vx, vy);
                    } else {
                        __half2 hv = {__float2half_rn(vx), __float2half_rn(vy)};
                        __half* o = (z == 0) ? outQ : (z == 1) ? outK : outV;
                        *(__half2*)(o + idx) = hv;
                    }
                }
            }
        }
    }
}

// ================= fp16 HMMA flash attention (causal, cp.async 2-stage) ======
// Q pre-scaled by QSCALE; softmax in base-2 (ex2).
#define AQ    128
#define AKV   64
#define APAD  72
#define FARR  (AKV * APAD * 2)     // 9216 bytes per K/V array
#define FSTG  (2 * FARR)           // 18432 bytes per stage (K, V)
#define FSMEM (2 * FSTG)           // 36864 bytes

__global__ __launch_bounds__(256, 2) void flash_hmma_kernel(
    const __half* __restrict__ Qh, const __half* __restrict__ Kh,
    const __half* __restrict__ Vh, __half* __restrict__ Oh)
{
    extern __shared__ __align__(16) char fsm[];
    const uint32_t uS = smem_u32(fsm);

    const int tid  = threadIdx.x;
    const int wid  = tid >> 5;
    const int lane = tid & 31;
    const int bh = blockIdx.y;
    const int b  = bh >> 4;
    const int h  = bh & 15;
    const int q0 = (gridDim.x - 1 - blockIdx.x) * AQ;   // longest CTAs first
    const size_t rowBase = (size_t)b * SLEN;
    const int colOff = h * HDIM;

    // ---- stage Q tile ----
#pragma unroll
    for (int it = 0; it < 4; it++) {
        const int id = tid + it * 256;
        const int r  = id >> 3;
        const int c  = id & 7;
        const int gq = q0 + r;
        uint4 v = make_uint4(0, 0, 0, 0);
        if (gq < SLEN)
            v = *(const uint4*)(Qh + (rowBase + gq) * NSTATE + colOff + c * 8);
        *(uint4*)(fsm + (r * APAD + c * 8) * 2) = v;
    }
    __syncthreads();

    const int aRow = lane & 15, aKof = (lane >> 4) * 8;
    const int wq0 = wid * 16;
    uint32_t qf[4][4];
#pragma unroll
    for (int ks = 0; ks < 4; ks++) {
        const uint32_t off = (uint32_t)((wq0 + aRow) * APAD + ks * 16 + aKof) * 2;
        LDSM_X4(qf[ks][0], qf[ks][1], qf[ks][2], qf[ks][3], uS + off);
    }
    __syncthreads();

#define FA_ISSUE(t, stg) do {                                                    \
        const int j0_ = (t) * AKV;                                               \
        const uint32_t sb = uS + (stg) * FSTG;                                   \
        _Pragma("unroll")                                                        \
        for (int it = 0; it < 2; it++) {                                         \
            const int id = tid + it * 256;                                       \
            const int r  = id >> 3;                                              \
            const int c  = id & 7;                                               \
            const int gk = j0_ + r;                                              \
            const int nb = (gk < SLEN) ? 16 : 0;                                 \
            const size_t off = (rowBase + gk) * NSTATE + colOff + c * 8;         \
            const uint32_t so = (uint32_t)(r * APAD + c * 8) * 2;                \
            CP16(sb + 0 * FARR + so, Kh + off, nb);                              \
            CP16(sb + 1 * FARR + so, Vh + off, nb);                              \
        }                                                                        \
        CP_COMMIT();                                                             \
    } while (0)

    const int gqa = q0 + wq0 + (lane >> 2);
    float mr0 = -1e30f, mr1 = -1e30f, l0 = 0.f, l1 = 0.f;
    float oacc[8][4];
#pragma unroll
    for (int i = 0; i < 8; i++)
#pragma unroll
        for (int q = 0; q < 4; q++) oacc[i][q] = 0.f;

    const int bNof = ((lane >> 4) * 8) + (lane & 7);
    const int bKof = ((lane >> 3) & 1) * 8;
    const int vRow = ((lane >> 3) & 1) * 8 + (lane & 7);
    const int vCof = (lane >> 4) * 8;

    const int tEnd = min(q0 + AQ - 1, SLEN - 1) / AKV;
    FA_ISSUE(0, 0);

    for (int t = 0; t <= tEnd; t++) {
        const int j0 = t * AKV;
        if (t + 1 <= tEnd) { FA_ISSUE(t + 1, (t + 1) & 1); CP_WAIT1(); }
        else               { CP_WAIT0(); }
        __syncthreads();

        const uint32_t sb = uS + (t & 1) * FSTG;
        const uint32_t uK = sb, uV = sb + FARR;

        if (j0 <= q0 + wq0 + 15) {
            // ---- S = Q K^T (fp16, Q pre-scaled to base-2 domain) ----
            float S[8][4];
#pragma unroll
            for (int nt = 0; nt < 8; nt++)
#pragma unroll
                for (int q = 0; q < 4; q++) S[nt][q] = 0.f;
#pragma unroll
            for (int ks = 0; ks < 4; ks++) {
                uint32_t kf[8][2];
#pragma unroll
                for (int np = 0; np < 4; np++) {
                    const uint32_t off =
                        (uint32_t)((np * 16 + bNof) * APAD + ks * 16 + bKof) * 2;
                    LDSM_X4(kf[np * 2][0], kf[np * 2][1],
                            kf[np * 2 + 1][0], kf[np * 2 + 1][1], uK + off);
                }
#pragma unroll
                for (int nt = 0; nt < 8; nt++)
                    MMA_F16(S[nt][0], S[nt][1], S[nt][2], S[nt][3],
                            qf[ks][0], qf[ks][1], qf[ks][2], qf[ks][3],
                            kf[nt][0], kf[nt][1]);
            }
            // ---- masking: fast path when warp's tile is fully unmasked ----
            const bool needMask = (j0 + AKV - 1 > q0 + wq0) || (j0 + AKV > SLEN);
            float mx0 = mr0, mx1 = mr1;
            if (needMask) {
                const int jc = j0 + 2 * (lane & 3);
#pragma unroll
                for (int nt = 0; nt < 8; nt++) {
#pragma unroll
                    for (int q = 0; q < 4; q++) {
                        const int jg  = jc + nt * 8 + (q & 1);
                        const int row = (q < 2) ? gqa : gqa + 8;
                        const bool ok = (jg <= row) && (jg < SLEN);
                        const float sv = ok ? S[nt][q] : -1e30f;
                        S[nt][q] = sv;
                        if (q < 2) mx0 = fmaxf(mx0, sv); else mx1 = fmaxf(mx1, sv);
                    }
                }
            } else {
#pragma unroll
                for (int nt = 0; nt < 8; nt++) {
                    mx0 = fmaxf(mx0, fmaxf(S[nt][0], S[nt][1]));
                    mx1 = fmaxf(mx1, fmaxf(S[nt][2], S[nt][3]));
                }
            }
            mx0 = fmaxf(mx0, __shfl_xor_sync(0xffffffffu, mx0, 1));
            mx0 = fmaxf(mx0, __shfl_xor_sync(0xffffffffu, mx0, 2));
            mx1 = fmaxf(mx1, __shfl_xor_sync(0xffffffffu, mx1, 1));
            mx1 = fmaxf(mx1, __shfl_xor_sync(0xffffffffu, mx1, 2));
            const float corr0 = ex2f(mr0 - mx0);
            const float corr1 = ex2f(mr1 - mx1);
            mr0 = mx0; mr1 = mx1;
            float ps0 = 0.f, ps1 = 0.f;
#pragma unroll
            for (int nt = 0; nt < 8; nt++) {
#pragma unroll
                for (int q = 0; q < 4; q++) {
                    const float p = ex2f(S[nt][q] - ((q < 2) ? mx0 : mx1));
                    S[nt][q] = p;
                    if (q < 2) ps0 += p; else ps1 += p;
                }
            }
            ps0 += __shfl_xor_sync(0xffffffffu, ps0, 1);
            ps0 += __shfl_xor_sync(0xffffffffu, ps0, 2);
            ps1 += __shfl_xor_sync(0xffffffffu, ps1, 1);
            ps1 += __shfl_xor_sync(0xffffffffu, ps1, 2);
            l0 = l0 * corr0 + ps0;
            l1 = l1 * corr1 + ps1;
#pragma unroll
            for (int nt = 0; nt < 8; nt++) {
                oacc[nt][0] *= corr0; oacc[nt][1] *= corr0;
                oacc[nt][2] *= corr1; oacc[nt][3] *= corr1;
            }
            // ---- O += P V (fp16) ----
#pragma unroll
            for (int ks2 = 0; ks2 < 4; ks2++) {
                uint32_t a0, a1, a2, a3;
                PACK_H2(a0, S[2 * ks2][0],     S[2 * ks2][1]);
                PACK_H2(a1, S[2 * ks2][2],     S[2 * ks2][3]);
                PACK_H2(a2, S[2 * ks2 + 1][0], S[2 * ks2 + 1][1]);
                PACK_H2(a3, S[2 * ks2 + 1][2], S[2 * ks2 + 1][3]);
#pragma unroll
                for (int dp = 0; dp < 4; dp++) {
                    uint32_t v0, v1, v2, v3;
                    const uint32_t off =
                        (uint32_t)((ks2 * 16 + vRow) * APAD + dp * 16 + vCof) * 2;
                    LDSM_X4_T(v0, v1, v2, v3, uV + off);
                    MMA_F16(oacc[2 * dp][0], oacc[2 * dp][1],
                            oacc[2 * dp][2], oacc[2 * dp][3],
                            a0, a1, a2, a3, v0, v1);
                    MMA_F16(oacc[2 * dp + 1][0], oacc[2 * dp + 1][1],
                            oacc[2 * dp + 1][2], oacc[2 * dp + 1][3],
                            a0, a1, a2, a3, v2, v3);
                }
            }
        }
        __syncthreads();
    }
#undef FA_ISSUE

    const float inv0 = (l0 > 0.f) ? 1.f / l0 : 0.f;
    const float inv1 = (l1 > 0.f) ? 1.f / l1 : 0.f;
#pragma unroll
    for (int nt = 0; nt < 8; nt++) {
        const int d = colOff + nt * 8 + 2 * (lane & 3);
        if (gqa < SLEN) {
            __half2 hv = {__float2half_rn(oacc[nt][0] * inv0),
                          __float2half_rn(oacc[nt][1] * inv0)};
            *(__half2*)(Oh + (rowBase + gqa) * NSTATE + d) = hv;
        }
        if (gqa + 8 < SLEN) {
            __half2 hv = {__float2half_rn(oacc[nt][2] * inv1),
                          __float2half_rn(oacc[nt][3] * inv1)};
            *(__half2*)(Oh + (rowBase + gqa + 8) * NSTATE + d) = hv;
        }
    }
}

// ---------------- launch -----------------------------------------------------
extern "C" void kernel_launch(void* const* d_in, const int* in_sizes, int n_in,
                              void* d_out, int out_size)
{
    const float* x  = (const float*)d_in[0];
    const float* Wq = (const float*)d_in[2];
    const float* bq = (const float*)d_in[3];
    const float* Wk = (const float*)d_in[4];
    const float* Wv = (const float*)d_in[5];
    const float* bv = (const float*)d_in[6];
    const float* Wo = (const float*)d_in[7];
    const float* bo = (const float*)d_in[8];
    float* out = (float*)d_out;

    __half *xh, *qh, *kh, *vh, *oh, *wh;
    cudaGetSymbolAddress((void**)&xh, g_Xh);
    cudaGetSymbolAddress((void**)&qh, g_Qh);
    cudaGetSymbolAddress((void**)&kh, g_Kh);
    cudaGetSymbolAddress((void**)&vh, g_Vh);
    cudaGetSymbolAddress((void**)&oh, g_Oh);
    cudaGetSymbolAddress((void**)&wh, g_Wh);
    const size_t WSZ = (size_t)NSTATE * NSTATE;

    cudaFuncSetAttribute(gemm_f16_kernel<0>,
                         cudaFuncAttributeMaxDynamicSharedMemorySize, GSMEM2);
    cudaFuncSetAttribute(gemm_f16_kernel<1>,
                         cudaFuncAttributeMaxDynamicSharedMemorySize, GSMEM2);
    cudaFuncSetAttribute(flash_hmma_kernel,
                         cudaFuncAttributeMaxDynamicSharedMemorySize, FSMEM);

    const int xn4 = MROWS * NSTATE / 4;
    const int wn4 = NSTATE * NSTATE / 4;
    cvt_f16_kernel<<<dim3((xn4 + 255) / 256, 1), 256>>>(
        x, nullptr, nullptr, nullptr, xh, 0, xn4);
    cvt_f16_kernel<<<dim3((wn4 + 255) / 256, 4), 256>>>(
        Wq, Wk, Wv, Wo, wh, WSZ, wn4);

    const dim3 qkvgrid(NSTATE / 128, (MROWS + 127) / 128, 3);
    gemm_f16_kernel<0><<<qkvgrid, 256, GSMEM2>>>(
        xh, wh, bq, bv, bo, qh, kh, vh, nullptr, MROWS);

    const dim3 agrid((SLEN + AQ - 1) / AQ, BATCH * NHEAD);
    flash_hmma_kernel<<<agrid, 256, FSMEM>>>(qh, kh, vh, oh);

    const dim3 ogrid(NSTATE / 128, (MROWS + 127) / 128, 1);
    gemm_f16_kernel<1><<<ogrid, 256, GSMEM2>>>(
        oh, wh, bq, bv, bo, nullptr, nullptr, nullptr, out, MROWS);
}

// round 11
// speedup vs baseline: 2.6418x; 1.1473x over previous
#include <cuda_runtime.h>
#include <cuda_bf16.h>
#include <cuda_fp16.h>
#include <cstdint>

#define BATCH  8
#define SLEN   1500
#define NSTATE 1024
#define NHEAD  16
#define HDIM   64
#define MROWS  (BATCH * SLEN)   // 12000

// scale folded into Q projection: 1/sqrt(64) * log2(e)
#define QSCALE 0.18033688011112042f

// ---------------- scratch (static device globals; no allocation) -------------
__device__ __half g_Xh[(size_t)MROWS * NSTATE];
__device__ __half g_Qh[(size_t)MROWS * NSTATE];
__device__ __half g_Kh[(size_t)MROWS * NSTATE];
__device__ __half g_Vh[(size_t)MROWS * NSTATE];
__device__ __half g_Oh[(size_t)MROWS * NSTATE];
__device__ __half g_Wh[4][(size_t)NSTATE * NSTATE];

__device__ __forceinline__ uint32_t smem_u32(const void* p) {
    uint32_t a;
    asm("{ .reg .u64 t; cvta.to.shared.u64 t, %1; cvt.u32.u64 %0, t; }"
        : "=r"(a) : "l"(p));
    return a;
}
__device__ __forceinline__ float ex2f(float x) {
    float r;
    asm("ex2.approx.f32 %0, %1;" : "=f"(r) : "f"(x));
    return r;
}

#define LDSM_X4(r0, r1, r2, r3, addr)                                            \
    asm volatile("ldmatrix.sync.aligned.m8n8.x4.shared.b16 {%0,%1,%2,%3}, [%4];" \
                 : "=r"(r0), "=r"(r1), "=r"(r2), "=r"(r3) : "r"(addr))

#define LDSM_X4_T(r0, r1, r2, r3, addr)                                          \
    asm volatile("ldmatrix.sync.aligned.m8n8.x4.trans.shared.b16 {%0,%1,%2,%3}, [%4];" \
                 : "=r"(r0), "=r"(r1), "=r"(r2), "=r"(r3) : "r"(addr))

#define MMA_F16(c0, c1, c2, c3, a0, a1, a2, a3, b0, b1)                          \
    asm volatile("mma.sync.aligned.m16n8k16.row.col.f32.f16.f16.f32 "            \
                 "{%0,%1,%2,%3}, {%4,%5,%6,%7}, {%8,%9}, {%0,%1,%2,%3};"         \
                 : "+f"(c0), "+f"(c1), "+f"(c2), "+f"(c3)                        \
                 : "r"(a0), "r"(a1), "r"(a2), "r"(a3), "r"(b0), "r"(b1))

#define PACK_H2(d, vlo, vhi)                                                     \
    asm("cvt.rn.f16x2.f32 %0, %1, %2;" : "=r"(d) : "f"(vhi), "f"(vlo))

#define CP16(dst, src, nbytes)                                                   \
    asm volatile("cp.async.cg.shared.global [%0], [%1], 16, %2;"                 \
                 :: "r"(dst), "l"(src), "r"(nbytes))
#define CP_COMMIT() asm volatile("cp.async.commit_group;" ::: "memory")
#define CP_WAIT1()  asm volatile("cp.async.wait_group 1;" ::: "memory")
#define CP_WAIT0()  asm volatile("cp.async.wait_group 0;" ::: "memory")

// ======================= convert fp32 -> fp16 ================================
__global__ __launch_bounds__(256) void cvt_f16_kernel(
    const float* __restrict__ in0, const float* __restrict__ in1,
    const float* __restrict__ in2, const float* __restrict__ in3,
    __half* __restrict__ o, size_t zstride, int n4)
{
    const int z = blockIdx.y;
    const float* in = (z == 0) ? in0 : (z == 1) ? in1 : (z == 2) ? in2 : in3;
    o += z * zstride;
    int i = blockIdx.x * blockDim.x + threadIdx.x;
    if (i < n4) {
        float4 v = *(const float4*)(in + (size_t)i * 4);
        __half2 h0 = {__float2half_rn(v.x), __float2half_rn(v.y)};
        __half2 h1 = {__float2half_rn(v.z), __float2half_rn(v.w)};
        *(__half2*)(o + (size_t)i * 4)     = h0;
        *(__half2*)(o + (size_t)i * 4 + 2) = h1;
    }
}

// ===== fp16 single-MMA GEMM (2-stage cp.async, BK=64) ========================
// PASS 0: grid.z z in {0:Q(+bq, *QSCALE), 1:K, 2:V(+bv)} -> fp16 outs
// PASS 1: O gemm -> fp32 out (+bo)
#define GBK     64
#define GPAD    72
#define GK_ITERS (NSTATE / GBK)            // 16
#define ARR_B   (128 * GPAD * 2)           // 18432 bytes per array
#define STG2_B  (2 * ARR_B)                // 36864 bytes per stage
#define GSMEM2  (2 * STG2_B)               // 73728 bytes

template <int PASS>
__global__ __launch_bounds__(256) void gemm_f16_kernel(
    const __half* __restrict__ A, const __half* __restrict__ W,
    const float* __restrict__ bq, const float* __restrict__ bv,
    const float* __restrict__ bo,
    __half* __restrict__ outQ, __half* __restrict__ outK,
    __half* __restrict__ outV, float* __restrict__ outF, int M)
{
    extern __shared__ __align__(16) char dsm[];
    const int z = (PASS == 0) ? blockIdx.z : 3;
    const __half* B = W + (size_t)z * NSTATE * NSTATE;
    const float* bias = (PASS == 1) ? bo : ((z == 0) ? bq : (z == 2) ? bv : nullptr);

    const int tid  = threadIdx.x;
    const int wid  = tid >> 5;
    const int lane = tid & 31;
    const int m0 = blockIdx.y * 128;
    const int n0 = blockIdx.x * 128;
    const int mbase = (wid >> 2) * 64;
    const int nbase = (wid & 3) * 32;
    const uint32_t uBase = smem_u32(dsm);

    float acc[4][4][4];
#pragma unroll
    for (int i = 0; i < 4; i++)
#pragma unroll
        for (int j = 0; j < 4; j++)
#pragma unroll
            for (int q = 0; q < 4; q++) acc[i][j][q] = 0.f;

    // loader: 1024 16B-chunks per array, 4 per thread (rows lrow+32i)
    const int lrow = tid >> 3;          // 0..31
    const int lc   = (tid & 7) * 8;     // 0..56
    int      okA[4];
    size_t   ga[4], gb[4];
    uint32_t so[4];
#pragma unroll
    for (int i = 0; i < 4; i++) {
        const int r = lrow + i * 32;
        okA[i] = (m0 + r < M) ? 16 : 0;
        ga[i]  = (size_t)(m0 + r) * NSTATE + lc;
        gb[i]  = (size_t)(n0 + r) * NSTATE + lc;
        so[i]  = (uint32_t)(r * GPAD + lc) * 2;
    }

#define ISSUE2(kit, stg) do {                                                    \
        const int k0_ = (kit) * GBK;                                             \
        const uint32_t sb = uBase + (stg) * STG2_B;                              \
        _Pragma("unroll")                                                        \
        for (int i = 0; i < 4; i++)                                              \
            CP16(sb + 0 * ARR_B + so[i], A + ga[i] + k0_, okA[i]);               \
        _Pragma("unroll")                                                        \
        for (int i = 0; i < 4; i++)                                              \
            CP16(sb + 1 * ARR_B + so[i], B + gb[i] + k0_, 16);                   \
        CP_COMMIT();                                                             \
    } while (0)

    ISSUE2(0, 0);

    const int aRow = lane & 15, aKof = (lane >> 4) * 8;
    const int bNof = ((lane >> 4) * 8) + (lane & 7);
    const int bKof = ((lane >> 3) & 1) * 8;

    for (int kit = 0; kit < GK_ITERS; kit++) {
        if (kit + 1 < GK_ITERS) { ISSUE2(kit + 1, (kit + 1) & 1); CP_WAIT1(); }
        else                    { CP_WAIT0(); }
        __syncthreads();

        const uint32_t sb = uBase + (kit & 1) * STG2_B;
        const uint32_t uA = sb, uB = sb + ARR_B;
#pragma unroll
        for (int ks = 0; ks < 4; ks++) {
            const int kof = ks * 16;
            uint32_t a[4][4];
#pragma unroll
            for (int mt = 0; mt < 4; mt++) {
                const uint32_t off =
                    (uint32_t)((mbase + mt * 16 + aRow) * GPAD + kof + aKof) * 2;
                LDSM_X4(a[mt][0], a[mt][1], a[mt][2], a[mt][3], uA + off);
            }
            uint32_t b[4][2];
#pragma unroll
            for (int np = 0; np < 2; np++) {
                const uint32_t off =
                    (uint32_t)((nbase + np * 16 + bNof) * GPAD + kof + bKof) * 2;
                LDSM_X4(b[np * 2][0], b[np * 2][1], b[np * 2 + 1][0], b[np * 2 + 1][1],
                        uB + off);
            }
#pragma unroll
            for (int mt = 0; mt < 4; mt++)
#pragma unroll
                for (int nt = 0; nt < 4; nt++) {
                    float* c4 = acc[mt][nt];
                    MMA_F16(c4[0], c4[1], c4[2], c4[3],
                            a[mt][0], a[mt][1], a[mt][2], a[mt][3],
                            b[nt][0], b[nt][1]);
                }
        }
        __syncthreads();
    }
#undef ISSUE2

    const int lr = lane >> 2;
    const int lc2 = (lane & 3) * 2;
#pragma unroll
    for (int mt = 0; mt < 4; mt++) {
#pragma unroll
        for (int half_ = 0; half_ < 2; half_++) {
            const int gm = m0 + mbase + mt * 16 + half_ * 8 + lr;
            if (gm < M) {
#pragma unroll
                for (int nt = 0; nt < 4; nt++) {
                    const int gn = n0 + nbase + nt * 8 + lc2;
                    float vx = acc[mt][nt][half_ * 2 + 0];
                    float vy = acc[mt][nt][half_ * 2 + 1];
                    if (bias) { vx += bias[gn]; vy += bias[gn + 1]; }
                    if (PASS == 0 && z == 0) { vx *= QSCALE; vy *= QSCALE; }
                    const size_t idx = (size_t)gm * NSTATE + gn;
                    if (PASS == 1) {
                        *(float2*)(outF + idx) = make_float2(vx, vy);
                    } else {
                        __half2 hv = {__float2half_rn(vx), __float2half_rn(vy)};
                        __half* o = (z == 0) ? outQ : (z == 1) ? outK : outV;
                        *(__half2*)(o + idx) = hv;
                    }
                }
            }
        }
    }
}

// ================= fp16 HMMA flash attention (causal) ========================
// AQ=64, 128 threads, 4 CTAs/SM. Q pre-scaled; base-2 softmax.
#define AQ    64
#define AKV   64
#define APAD  72
#define FARR  (AKV * APAD * 2)     // 9216 bytes per K/V array
#define FSTG  (2 * FARR)           // 18432 bytes per stage (K, V)
#define FSMEM (2 * FSTG)           // 36864 bytes

__global__ __launch_bounds__(128, 4) void flash_hmma_kernel(
    const __half* __restrict__ Qh, const __half* __restrict__ Kh,
    const __half* __restrict__ Vh, __half* __restrict__ Oh)
{
    extern __shared__ __align__(16) char fsm[];
    const uint32_t uS = smem_u32(fsm);

    const int tid  = threadIdx.x;
    const int wid  = tid >> 5;
    const int lane = tid & 31;
    const int bh = blockIdx.y;
    const int b  = bh >> 4;
    const int h  = bh & 15;
    const int q0 = (gridDim.x - 1 - blockIdx.x) * AQ;   // longest CTAs first
    const size_t rowBase = (size_t)b * SLEN;
    const int colOff = h * HDIM;

    // ---- stage Q tile (64x64 fp16) ----
#pragma unroll
    for (int it = 0; it < 4; it++) {
        const int id = tid + it * 128;     // 0..511
        const int r  = id >> 3;
        const int c  = id & 7;
        const int gq = q0 + r;
        uint4 v = make_uint4(0, 0, 0, 0);
        if (gq < SLEN)
            v = *(const uint4*)(Qh + (rowBase + gq) * NSTATE + colOff + c * 8);
        *(uint4*)(fsm + (r * APAD + c * 8) * 2) = v;
    }
    __syncthreads();

    const int aRow = lane & 15, aKof = (lane >> 4) * 8;
    const int wq0 = wid * 16;
    uint32_t qf[4][4];
#pragma unroll
    for (int ks = 0; ks < 4; ks++) {
        const uint32_t off = (uint32_t)((wq0 + aRow) * APAD + ks * 16 + aKof) * 2;
        LDSM_X4(qf[ks][0], qf[ks][1], qf[ks][2], qf[ks][3], uS + off);
    }
    __syncthreads();

#define FA_ISSUE(t, stg) do {                                                    \
        const int j0_ = (t) * AKV;                                               \
        const uint32_t sb = uS + (stg) * FSTG;                                   \
        _Pragma("unroll")                                                        \
        for (int it = 0; it < 4; it++) {                                         \
            const int id = tid + it * 128;                                       \
            const int r  = id >> 3;                                              \
            const int c  = id & 7;                                               \
            const int gk = j0_ + r;                                              \
            const int nb = (gk < SLEN) ? 16 : 0;                                 \
            const size_t off = (rowBase + gk) * NSTATE + colOff + c * 8;         \
            const uint32_t so_ = (uint32_t)(r * APAD + c * 8) * 2;               \
            CP16(sb + 0 * FARR + so_, Kh + off, nb);                             \
            CP16(sb + 1 * FARR + so_, Vh + off, nb);                             \
        }                                                                        \
        CP_COMMIT();                                                             \
    } while (0)

    const int gqa = q0 + wq0 + (lane >> 2);
    float mr0 = -1e30f, mr1 = -1e30f, l0 = 0.f, l1 = 0.f;
    float oacc[8][4];
#pragma unroll
    for (int i = 0; i < 8; i++)
#pragma unroll
        for (int q = 0; q < 4; q++) oacc[i][q] = 0.f;

    const int bNof = ((lane >> 4) * 8) + (lane & 7);
    const int bKof = ((lane >> 3) & 1) * 8;
    const int vRow = ((lane >> 3) & 1) * 8 + (lane & 7);
    const int vCof = (lane >> 4) * 8;

    const int tEnd = min(q0 + AQ - 1, SLEN - 1) / AKV;
    FA_ISSUE(0, 0);

    for (int t = 0; t <= tEnd; t++) {
        const int j0 = t * AKV;
        if (t + 1 <= tEnd) { FA_ISSUE(t + 1, (t + 1) & 1); CP_WAIT1(); }
        else               { CP_WAIT0(); }
        __syncthreads();

        const uint32_t sb = uS + (t & 1) * FSTG;
        const uint32_t uK = sb, uV = sb + FARR;

        if (j0 <= q0 + wq0 + 15) {
            // ---- S = Q K^T (fp16, Q pre-scaled to base-2 domain) ----
            float S[8][4];
#pragma unroll
            for (int nt = 0; nt < 8; nt++)
#pragma unroll
                for (int q = 0; q < 4; q++) S[nt][q] = 0.f;
#pragma unroll
            for (int ks = 0; ks < 4; ks++) {
                uint32_t kf[8][2];
#pragma unroll
                for (int np = 0; np < 4; np++) {
                    const uint32_t off =
                        (uint32_t)((np * 16 + bNof) * APAD + ks * 16 + bKof) * 2;
                    LDSM_X4(kf[np * 2][0], kf[np * 2][1],
                            kf[np * 2 + 1][0], kf[np * 2 + 1][1], uK + off);
                }
#pragma unroll
                for (int nt = 0; nt < 8; nt++)
                    MMA_F16(S[nt][0], S[nt][1], S[nt][2], S[nt][3],
                            qf[ks][0], qf[ks][1], qf[ks][2], qf[ks][3],
                            kf[nt][0], kf[nt][1]);
            }
            // ---- masking: fast path when warp's tile is fully unmasked ----
            const bool needMask = (j0 + AKV - 1 > q0 + wq0) || (j0 + AKV > SLEN);
            float mx0 = mr0, mx1 = mr1;
            if (needMask) {
                const int jc = j0 + 2 * (lane & 3);
#pragma unroll
                for (int nt = 0; nt < 8; nt++) {
#pragma unroll
                    for (int q = 0; q < 4; q++) {
                        const int jg  = jc + nt * 8 + (q & 1);
                        const int row = (q < 2) ? gqa : gqa + 8;
                        const bool ok = (jg <= row) && (jg < SLEN);
                        const float sv = ok ? S[nt][q] : -1e30f;
                        S[nt][q] = sv;
                        if (q < 2) mx0 = fmaxf(mx0, sv); else mx1 = fmaxf(mx1, sv);
                    }
                }
            } else {
#pragma unroll
                for (int nt = 0; nt < 8; nt++) {
                    mx0 = fmaxf(mx0, fmaxf(S[nt][0], S[nt][1]));
                    mx1 = fmaxf(mx1, fmaxf(S[nt][2], S[nt][3]));
                }
            }
            mx0 = fmaxf(mx0, __shfl_xor_sync(0xffffffffu, mx0, 1));
            mx0 = fmaxf(mx0, __shfl_xor_sync(0xffffffffu, mx0, 2));
            mx1 = fmaxf(mx1, __shfl_xor_sync(0xffffffffu, mx1, 1));
            mx1 = fmaxf(mx1, __shfl_xor_sync(0xffffffffu, mx1, 2));
            const float corr0 = ex2f(mr0 - mx0);
            const float corr1 = ex2f(mr1 - mx1);
            mr0 = mx0; mr1 = mx1;
            float ps0 = 0.f, ps1 = 0.f;
#pragma unroll
            for (int nt = 0; nt < 8; nt++) {
#pragma unroll
                for (int q = 0; q < 4; q++) {
                    const float p = ex2f(S[nt][q] - ((q < 2) ? mx0 : mx1));
                    S[nt][q] = p;
                    if (q < 2) ps0 += p; else ps1 += p;
                }
            }
            ps0 += __shfl_xor_sync(0xffffffffu, ps0, 1);
            ps0 += __shfl_xor_sync(0xffffffffu, ps0, 2);
            ps1 += __shfl_xor_sync(0xffffffffu, ps1, 1);
            ps1 += __shfl_xor_sync(0xffffffffu, ps1, 2);
            l0 = l0 * corr0 + ps0;
            l1 = l1 * corr1 + ps1;
#pragma unroll
            for (int nt = 0; nt < 8; nt++) {
                oacc[nt][0] *= corr0; oacc[nt][1] *= corr0;
                oacc[nt][2] *= corr1; oacc[nt][3] *= corr1;
            }
            // ---- O += P V (fp16) ----
#pragma unroll
            for (int ks2 = 0; ks2 < 4; ks2++) {
                uint32_t a0, a1, a2, a3;
                PACK_H2(a0, S[2 * ks2][0],     S[2 * ks2][1]);
                PACK_H2(a1, S[2 * ks2][2],     S[2 * ks2][3]);
                PACK_H2(a2, S[2 * ks2 + 1][0], S[2 * ks2 + 1][1]);
                PACK_H2(a3, S[2 * ks2 + 1][2], S[2 * ks2 + 1][3]);
#pragma unroll
                for (int dp = 0; dp < 4; dp++) {
                    uint32_t v0, v1, v2, v3;
                    const uint32_t off =
                        (uint32_t)((ks2 * 16 + vRow) * APAD + dp * 16 + vCof) * 2;
                    LDSM_X4_T(v0, v1, v2, v3, uV + off);
                    MMA_F16(oacc[2 * dp][0], oacc[2 * dp][1],
                            oacc[2 * dp][2], oacc[2 * dp][3],
                            a0, a1, a2, a3, v0, v1);
                    MMA_F16(oacc[2 * dp + 1][0], oacc[2 * dp + 1][1],
                            oacc[2 * dp + 1][2], oacc[2 * dp + 1][3],
                            a0, a1, a2, a3, v2, v3);
                }
            }
        }
        __syncthreads();
    }
#undef FA_ISSUE

    const float inv0 = (l0 > 0.f) ? 1.f / l0 : 0.f;
    const float inv1 = (l1 > 0.f) ? 1.f / l1 : 0.f;
#pragma unroll
    for (int nt = 0; nt < 8; nt++) {
        const int d = colOff + nt * 8 + 2 * (lane & 3);
        if (gqa < SLEN) {
            __half2 hv = {__float2half_rn(oacc[nt][0] * inv0),
                          __float2half_rn(oacc[nt][1] * inv0)};
            *(__half2*)(Oh + (rowBase + gqa) * NSTATE + d) = hv;
        }
        if (gqa + 8 < SLEN) {
            __half2 hv = {__float2half_rn(oacc[nt][2] * inv1),
                          __float2half_rn(oacc[nt][3] * inv1)};
            *(__half2*)(Oh + (rowBase + gqa + 8) * NSTATE + d) = hv;
        }
    }
}

// ---------------- launch -----------------------------------------------------
extern "C" void kernel_launch(void* const* d_in, const int* in_sizes, int n_in,
                              void* d_out, int out_size)
{
    const float* x  = (const float*)d_in[0];
    const float* Wq = (const float*)d_in[2];
    const float* bq = (const float*)d_in[3];
    const float* Wk = (const float*)d_in[4];
    const float* Wv = (const float*)d_in[5];
    const float* bv = (const float*)d_in[6];
    const float* Wo = (const float*)d_in[7];
    const float* bo = (const float*)d_in[8];
    float* out = (float*)d_out;

    __half *xh, *qh, *kh, *vh, *oh, *wh;
    cudaGetSymbolAddress((void**)&xh, g_Xh);
    cudaGetSymbolAddress((void**)&qh, g_Qh);
    cudaGetSymbolAddress((void**)&kh, g_Kh);
    cudaGetSymbolAddress((void**)&vh, g_Vh);
    cudaGetSymbolAddress((void**)&oh, g_Oh);
    cudaGetSymbolAddress((void**)&wh, g_Wh);
    const size_t WSZ = (size_t)NSTATE * NSTATE;

    cudaFuncSetAttribute(gemm_f16_kernel<0>,
                         cudaFuncAttributeMaxDynamicSharedMemorySize, GSMEM2);
    cudaFuncSetAttribute(gemm_f16_kernel<1>,
                         cudaFuncAttributeMaxDynamicSharedMemorySize, GSMEM2);
    cudaFuncSetAttribute(flash_hmma_kernel,
                         cudaFuncAttributeMaxDynamicSharedMemorySize, FSMEM);

    const int xn4 = MROWS * NSTATE / 4;
    const int wn4 = NSTATE * NSTATE / 4;
    cvt_f16_kernel<<<dim3((xn4 + 255) / 256, 1), 256>>>(
        x, nullptr, nullptr, nullptr, xh, 0, xn4);
    cvt_f16_kernel<<<dim3((wn4 + 255) / 256, 4), 256>>>(
        Wq, Wk, Wv, Wo, wh, WSZ, wn4);

    const dim3 qkvgrid(NSTATE / 128, (MROWS + 127) / 128, 3);
    gemm_f16_kernel<0><<<qkvgrid, 256, GSMEM2>>>(
        xh, wh, bq, bv, bo, qh, kh, vh, nullptr, MROWS);

    const dim3 agrid((SLEN + AQ - 1) / AQ, BATCH * NHEAD);   // 24 x 128
    flash_hmma_kernel<<<agrid, 128, FSMEM>>>(qh, kh, vh, oh);

    const dim3 ogrid(NSTATE / 128, (MROWS + 127) / 128, 1);
    gemm_f16_kernel<1><<<ogrid, 256, GSMEM2>>>(
        oh, wh, bq, bv, bo, nullptr, nullptr, nullptr, out, MROWS);
}

// round 13
// speedup vs baseline: 2.7120x; 1.0265x over previous
#include <cuda_runtime.h>
#include <cuda_bf16.h>
#include <cuda_fp16.h>
#include <cstdint>

#define BATCH  8
#define SLEN   1500
#define NSTATE 1024
#define NHEAD  16
#define HDIM   64
#define MROWS  (BATCH * SLEN)   // 12000

// scale folded into Q projection: 1/sqrt(64) * log2(e)
#define QSCALE 0.18033688011112042f
#define ONES_H2 0x3C003C00u     // half2(1.0, 1.0)

// ---------------- scratch (static device globals; no allocation) -------------
__device__ __half g_Xh[(size_t)MROWS * NSTATE];
__device__ __half g_Qh[(size_t)MROWS * NSTATE];
__device__ __half g_Kh[(size_t)MROWS * NSTATE];
__device__ __half g_Vh[(size_t)MROWS * NSTATE];
__device__ __half g_Oh[(size_t)MROWS * NSTATE];
__device__ __half g_Wh[4][(size_t)NSTATE * NSTATE];

__device__ __forceinline__ uint32_t smem_u32(const void* p) {
    uint32_t a;
    asm("{ .reg .u64 t; cvta.to.shared.u64 t, %1; cvt.u32.u64 %0, t; }"
        : "=r"(a) : "l"(p));
    return a;
}
__device__ __forceinline__ float ex2f(float x) {
    float r;
    asm("ex2.approx.f32 %0, %1;" : "=f"(r) : "f"(x));
    return r;
}

#define LDSM_X4(r0, r1, r2, r3, addr)                                            \
    asm volatile("ldmatrix.sync.aligned.m8n8.x4.shared.b16 {%0,%1,%2,%3}, [%4];" \
                 : "=r"(r0), "=r"(r1), "=r"(r2), "=r"(r3) : "r"(addr))

#define LDSM_X4_T(r0, r1, r2, r3, addr)                                          \
    asm volatile("ldmatrix.sync.aligned.m8n8.x4.trans.shared.b16 {%0,%1,%2,%3}, [%4];" \
                 : "=r"(r0), "=r"(r1), "=r"(r2), "=r"(r3) : "r"(addr))

#define MMA_F16(c0, c1, c2, c3, a0, a1, a2, a3, b0, b1)                          \
    asm volatile("mma.sync.aligned.m16n8k16.row.col.f32.f16.f16.f32 "            \
                 "{%0,%1,%2,%3}, {%4,%5,%6,%7}, {%8,%9}, {%0,%1,%2,%3};"         \
                 : "+f"(c0), "+f"(c1), "+f"(c2), "+f"(c3)                        \
                 : "r"(a0), "r"(a1), "r"(a2), "r"(a3), "r"(b0), "r"(b1))

#define PACK_H2(d, vlo, vhi)                                                     \
    asm("cvt.rn.f16x2.f32 %0, %1, %2;" : "=r"(d) : "f"(vhi), "f"(vlo))

#define EX2_H2(d, s)                                                             \
    asm("ex2.approx.f16x2 %0, %1;" : "=r"(d) : "r"(s))

#define CP16(dst, src, nbytes)                                                   \
    asm volatile("cp.async.cg.shared.global [%0], [%1], 16, %2;"                 \
                 :: "r"(dst), "l"(src), "r"(nbytes))
#define CP_COMMIT() asm volatile("cp.async.commit_group;" ::: "memory")
#define CP_WAIT1()  asm volatile("cp.async.wait_group 1;" ::: "memory")
#define CP_WAIT0()  asm volatile("cp.async.wait_group 0;" ::: "memory")

// ======================= convert fp32 -> fp16 ================================
__global__ __launch_bounds__(256) void cvt_f16_kernel(
    const float* __restrict__ in0, const float* __restrict__ in1,
    const float* __restrict__ in2, const float* __restrict__ in3,
    __half* __restrict__ o, size_t zstride, int n4)
{
    const int z = blockIdx.y;
    const float* in = (z == 0) ? in0 : (z == 1) ? in1 : (z == 2) ? in2 : in3;
    o += z * zstride;
    int i = blockIdx.x * blockDim.x + threadIdx.x;
    if (i < n4) {
        float4 v = *(const float4*)(in + (size_t)i * 4);
        __half2 h0 = {__float2half_rn(v.x), __float2half_rn(v.y)};
        __half2 h1 = {__float2half_rn(v.z), __float2half_rn(v.w)};
        *(__half2*)(o + (size_t)i * 4)     = h0;
        *(__half2*)(o + (size_t)i * 4 + 2) = h1;
    }
}

// ===== fp16 single-MMA GEMM (2-stage cp.async, BK=64) ========================
#define GBK     64
#define GPAD    72
#define GK_ITERS (NSTATE / GBK)            // 16
#define ARR_B   (128 * GPAD * 2)           // 18432 bytes per array
#define STG2_B  (2 * ARR_B)                // 36864 bytes per stage
#define GSMEM2  (2 * STG2_B)               // 73728 bytes

template <int PASS>
__global__ __launch_bounds__(256) void gemm_f16_kernel(
    const __half* __restrict__ A, const __half* __restrict__ W,
    const float* __restrict__ bq, const float* __restrict__ bv,
    const float* __restrict__ bo,
    __half* __restrict__ outQ, __half* __restrict__ outK,
    __half* __restrict__ outV, float* __restrict__ outF, int M)
{
    extern __shared__ __align__(16) char dsm[];
    const int z = (PASS == 0) ? blockIdx.z : 3;
    const __half* B = W + (size_t)z * NSTATE * NSTATE;
    const float* bias = (PASS == 1) ? bo : ((z == 0) ? bq : (z == 2) ? bv : nullptr);

    const int tid  = threadIdx.x;
    const int wid  = tid >> 5;
    const int lane = tid & 31;
    const int m0 = blockIdx.y * 128;
    const int n0 = blockIdx.x * 128;
    const int mbase = (wid >> 2) * 64;
    const int nbase = (wid & 3) * 32;
    const uint32_t uBase = smem_u32(dsm);

    float acc[4][4][4];
#pragma unroll
    for (int i = 0; i < 4; i++)
#pragma unroll
        for (int j = 0; j < 4; j++)
#pragma unroll
            for (int q = 0; q < 4; q++) acc[i][j][q] = 0.f;

    const int lrow = tid >> 3;
    const int lc   = (tid & 7) * 8;
    int      okA[4];
    size_t   ga[4], gb[4];
    uint32_t so[4];
#pragma unroll
    for (int i = 0; i < 4; i++) {
        const int r = lrow + i * 32;
        okA[i] = (m0 + r < M) ? 16 : 0;
        ga[i]  = (size_t)(m0 + r) * NSTATE + lc;
        gb[i]  = (size_t)(n0 + r) * NSTATE + lc;
        so[i]  = (uint32_t)(r * GPAD + lc) * 2;
    }

#define ISSUE2(kit, stg) do {                                                    \
        const int k0_ = (kit) * GBK;                                             \
        const uint32_t sb = uBase + (stg) * STG2_B;                              \
        _Pragma("unroll")                                                        \
        for (int i = 0; i < 4; i++)                                              \
            CP16(sb + 0 * ARR_B + so[i], A + ga[i] + k0_, okA[i]);               \
        _Pragma("unroll")                                                        \
        for (int i = 0; i < 4; i++)                                              \
            CP16(sb + 1 * ARR_B + so[i], B + gb[i] + k0_, 16);                   \
        CP_COMMIT();                                                             \
    } while (0)

    ISSUE2(0, 0);

    const int aRow = lane & 15, aKof = (lane >> 4) * 8;
    const int bNof = ((lane >> 4) * 8) + (lane & 7);
    const int bKof = ((lane >> 3) & 1) * 8;

    for (int kit = 0; kit < GK_ITERS; kit++) {
        if (kit + 1 < GK_ITERS) { ISSUE2(kit + 1, (kit + 1) & 1); CP_WAIT1(); }
        else                    { CP_WAIT0(); }
        __syncthreads();

        const uint32_t sb = uBase + (kit & 1) * STG2_B;
        const uint32_t uA = sb, uB = sb + ARR_B;
#pragma unroll
        for (int ks = 0; ks < 4; ks++) {
            const int kof = ks * 16;
            uint32_t a[4][4];
#pragma unroll
            for (int mt = 0; mt < 4; mt++) {
                const uint32_t off =
                    (uint32_t)((mbase + mt * 16 + aRow) * GPAD + kof + aKof) * 2;
                LDSM_X4(a[mt][0], a[mt][1], a[mt][2], a[mt][3], uA + off);
            }
            uint32_t b[4][2];
#pragma unroll
            for (int np = 0; np < 2; np++) {
                const uint32_t off =
                    (uint32_t)((nbase + np * 16 + bNof) * GPAD + kof + bKof) * 2;
                LDSM_X4(b[np * 2][0], b[np * 2][1], b[np * 2 + 1][0], b[np * 2 + 1][1],
                        uB + off);
            }
#pragma unroll
            for (int mt = 0; mt < 4; mt++)
#pragma unroll
                for (int nt = 0; nt < 4; nt++) {
                    float* c4 = acc[mt][nt];
                    MMA_F16(c4[0], c4[1], c4[2], c4[3],
                            a[mt][0], a[mt][1], a[mt][2], a[mt][3],
                            b[nt][0], b[nt][1]);
                }
        }
        __syncthreads();
    }
#undef ISSUE2

    const int lr = lane >> 2;
    const int lc2 = (lane & 3) * 2;
#pragma unroll
    for (int mt = 0; mt < 4; mt++) {
#pragma unroll
        for (int half_ = 0; half_ < 2; half_++) {
            const int gm = m0 + mbase + mt * 16 + half_ * 8 + lr;
            if (gm < M) {
#pragma unroll
                for (int nt = 0; nt < 4; nt++) {
                    const int gn = n0 + nbase + nt * 8 + lc2;
                    float vx = acc[mt][nt][half_ * 2 + 0];
                    float vy = acc[mt][nt][half_ * 2 + 1];
                    if (bias) { vx += bias[gn]; vy += bias[gn + 1]; }
                    if (PASS == 0 && z == 0) { vx *= QSCALE; vy *= QSCALE; }
                    const size_t idx = (size_t)gm * NSTATE + gn;
                    if (PASS == 1) {
                        *(float2*)(outF + idx) = make_float2(vx, vy);
                    } else {
                        __half2 hv = {__float2half_rn(vx), __float2half_rn(vy)};
                        __half* o = (z == 0) ? outQ : (z == 1) ? outK : outV;
                        *(__half2*)(o + idx) = hv;
                    }
                }
            }
        }
    }
}

// ================= fp16 HMMA flash attention (causal) ========================
// AQ=64, 128 threads. Q pre-scaled; base-2 softmax via ex2.f16x2;
// row sums via ones-MMA (tensor pipe does the cross-thread reduction).
#define AQ    64
#define AKV   64
#define APAD  72
#define FARR  (AKV * APAD * 2)     // 9216 bytes per K/V array
#define FSTG  (2 * FARR)           // 18432 bytes per stage (K, V)
#define FSMEM (2 * FSTG)           // 36864 bytes

__global__ __launch_bounds__(128, 4) void flash_hmma_kernel(
    const __half* __restrict__ Qh, const __half* __restrict__ Kh,
    const __half* __restrict__ Vh, __half* __restrict__ Oh)
{
    extern __shared__ __align__(16) char fsm[];
    const uint32_t uS = smem_u32(fsm);

    const int tid  = threadIdx.x;
    const int wid  = tid >> 5;
    const int lane = tid & 31;
    const int bh = blockIdx.y;
    const int b  = bh >> 4;
    const int h  = bh & 15;
    const int q0 = (gridDim.x - 1 - blockIdx.x) * AQ;   // longest CTAs first
    const size_t rowBase = (size_t)b * SLEN;
    const int colOff = h * HDIM;

    // ---- stage Q tile (64x64 fp16) ----
#pragma unroll
    for (int it = 0; it < 4; it++) {
        const int id = tid + it * 128;
        const int r  = id >> 3;
        const int c  = id & 7;
        const int gq = q0 + r;
        uint4 v = make_uint4(0, 0, 0, 0);
        if (gq < SLEN)
            v = *(const uint4*)(Qh + (rowBase + gq) * NSTATE + colOff + c * 8);
        *(uint4*)(fsm + (r * APAD + c * 8) * 2) = v;
    }
    __syncthreads();

    const int aRow = lane & 15, aKof = (lane >> 4) * 8;
    const int wq0 = wid * 16;
    uint32_t qf[4][4];
#pragma unroll
    for (int ks = 0; ks < 4; ks++) {
        const uint32_t off = (uint32_t)((wq0 + aRow) * APAD + ks * 16 + aKof) * 2;
        LDSM_X4(qf[ks][0], qf[ks][1], qf[ks][2], qf[ks][3], uS + off);
    }
    __syncthreads();

#define FA_ISSUE(t, stg) do {                                                    \
        const int j0_ = (t) * AKV;                                               \
        const uint32_t sb = uS + (stg) * FSTG;                                   \
        _Pragma("unroll")                                                        \
        for (int it = 0; it < 4; it++) {                                         \
            const int id = tid + it * 128;                                       \
            const int r  = id >> 3;                                              \
            const int c  = id & 7;                                               \
            const int gk = j0_ + r;                                              \
            const int nb = (gk < SLEN) ? 16 : 0;                                 \
            const size_t off = (rowBase + gk) * NSTATE + colOff + c * 8;         \
            const uint32_t so_ = (uint32_t)(r * APAD + c * 8) * 2;               \
            CP16(sb + 0 * FARR + so_, Kh + off, nb);                             \
            CP16(sb + 1 * FARR + so_, Vh + off, nb);                             \
        }                                                                        \
        CP_COMMIT();                                                             \
    } while (0)

    const int gqa = q0 + wq0 + (lane >> 2);
    float mr0 = -1e30f, mr1 = -1e30f, l0 = 0.f, l1 = 0.f;
    float oacc[8][4];
#pragma unroll
    for (int i = 0; i < 8; i++)
#pragma unroll
        for (int q = 0; q < 4; q++) oacc[i][q] = 0.f;

    const int bNof = ((lane >> 4) * 8) + (lane & 7);
    const int bKof = ((lane >> 3) & 1) * 8;
    const int vRow = ((lane >> 3) & 1) * 8 + (lane & 7);
    const int vCof = (lane >> 4) * 8;

    const int tEnd = min(q0 + AQ - 1, SLEN - 1) / AKV;
    FA_ISSUE(0, 0);

    for (int t = 0; t <= tEnd; t++) {
        const int j0 = t * AKV;
        if (t + 1 <= tEnd) { FA_ISSUE(t + 1, (t + 1) & 1); CP_WAIT1(); }
        else               { CP_WAIT0(); }
        __syncthreads();

        const uint32_t sb = uS + (t & 1) * FSTG;
        const uint32_t uK = sb, uV = sb + FARR;

        if (j0 <= q0 + wq0 + 15) {
            // ---- S = Q K^T (fp16, Q pre-scaled to base-2 domain) ----
            float S[8][4];
#pragma unroll
            for (int nt = 0; nt < 8; nt++)
#pragma unroll
                for (int q = 0; q < 4; q++) S[nt][q] = 0.f;
#pragma unroll
            for (int ks = 0; ks < 4; ks++) {
                uint32_t kf[8][2];
#pragma unroll
                for (int np = 0; np < 4; np++) {
                    const uint32_t off =
                        (uint32_t)((np * 16 + bNof) * APAD + ks * 16 + bKof) * 2;
                    LDSM_X4(kf[np * 2][0], kf[np * 2][1],
                            kf[np * 2 + 1][0], kf[np * 2 + 1][1], uK + off);
                }
#pragma unroll
                for (int nt = 0; nt < 8; nt++)
                    MMA_F16(S[nt][0], S[nt][1], S[nt][2], S[nt][3],
                            qf[ks][0], qf[ks][1], qf[ks][2], qf[ks][3],
                            kf[nt][0], kf[nt][1]);
            }
            // ---- masking + row max ----
            const bool needMask = (j0 + AKV - 1 > q0 + wq0) || (j0 + AKV > SLEN);
            float mx0 = mr0, mx1 = mr1;
            if (needMask) {
                const int jc = j0 + 2 * (lane & 3);
#pragma unroll
                for (int nt = 0; nt < 8; nt++) {
#pragma unroll
                    for (int q = 0; q < 4; q++) {
                        const int jg  = jc + nt * 8 + (q & 1);
                        const int row = (q < 2) ? gqa : gqa + 8;
                        const bool ok = (jg <= row) && (jg < SLEN);
                        const float sv = ok ? S[nt][q] : -1e30f;
                        S[nt][q] = sv;
                        if (q < 2) mx0 = fmaxf(mx0, sv); else mx1 = fmaxf(mx1, sv);
                    }
                }
            } else {
#pragma unroll
                for (int nt = 0; nt < 8; nt++) {
                    mx0 = fmaxf(mx0, fmaxf(S[nt][0], S[nt][1]));
                    mx1 = fmaxf(mx1, fmaxf(S[nt][2], S[nt][3]));
                }
            }
            mx0 = fmaxf(mx0, __shfl_xor_sync(0xffffffffu, mx0, 1));
            mx0 = fmaxf(mx0, __shfl_xor_sync(0xffffffffu, mx0, 2));
            mx1 = fmaxf(mx1, __shfl_xor_sync(0xffffffffu, mx1, 1));
            mx1 = fmaxf(mx1, __shfl_xor_sync(0xffffffffu, mx1, 2));
            const float corr0 = ex2f(mr0 - mx0);
            const float corr1 = ex2f(mr1 - mx1);
            mr0 = mx0; mr1 = mx1;

            // ---- sub(max) in fp32, pack half2, packed ex2 -> P fragments ----
            uint32_t Pl[8], Ph[8];
#pragma unroll
            for (int nt = 0; nt < 8; nt++) {
                uint32_t plo, phi;
                PACK_H2(plo, S[nt][0] - mx0, S[nt][1] - mx0);
                PACK_H2(phi, S[nt][2] - mx1, S[nt][3] - mx1);
                EX2_H2(Pl[nt], plo);
                EX2_H2(Ph[nt], phi);
            }
            // ---- row sums via ones-MMA (cross-thread reduction on tensor pipe)
            float sc0 = 0.f, sc1 = 0.f, sc2 = 0.f, sc3 = 0.f;
#pragma unroll
            for (int ks2 = 0; ks2 < 4; ks2++)
                MMA_F16(sc0, sc1, sc2, sc3,
                        Pl[2 * ks2], Ph[2 * ks2], Pl[2 * ks2 + 1], Ph[2 * ks2 + 1],
                        ONES_H2, ONES_H2);
            l0 = l0 * corr0 + sc0;
            l1 = l1 * corr1 + sc2;
#pragma unroll
            for (int nt = 0; nt < 8; nt++) {
                oacc[nt][0] *= corr0; oacc[nt][1] *= corr0;
                oacc[nt][2] *= corr1; oacc[nt][3] *= corr1;
            }
            // ---- O += P V (fragments already packed) ----
#pragma unroll
            for (int ks2 = 0; ks2 < 4; ks2++) {
                const uint32_t a0 = Pl[2 * ks2],     a1 = Ph[2 * ks2];
                const uint32_t a2 = Pl[2 * ks2 + 1], a3 = Ph[2 * ks2 + 1];
#pragma unroll
                for (int dp = 0; dp < 4; dp++) {
                    uint32_t v0, v1, v2, v3;
                    const uint32_t off =
                        (uint32_t)((ks2 * 16 + vRow) * APAD + dp * 16 + vCof) * 2;
                    LDSM_X4_T(v0, v1, v2, v3, uV + off);
                    MMA_F16(oacc[2 * dp][0], oacc[2 * dp][1],
                            oacc[2 * dp][2], oacc[2 * dp][3],
                            a0, a1, a2, a3, v0, v1);
                    MMA_F16(oacc[2 * dp + 1][0], oacc[2 * dp + 1][1],
                            oacc[2 * dp + 1][2], oacc[2 * dp + 1][3],
                            a0, a1, a2, a3, v2, v3);
                }
            }
        }
        __syncthreads();
    }
#undef FA_ISSUE

    const float inv0 = (l0 > 0.f) ? 1.f / l0 : 0.f;
    const float inv1 = (l1 > 0.f) ? 1.f / l1 : 0.f;
#pragma unroll
    for (int nt = 0; nt < 8; nt++) {
        const int d = colOff + nt * 8 + 2 * (lane & 3);
        if (gqa < SLEN) {
            __half2 hv = {__float2half_rn(oacc[nt][0] * inv0),
                          __float2half_rn(oacc[nt][1] * inv0)};
            *(__half2*)(Oh + (rowBase + gqa) * NSTATE + d) = hv;
        }
        if (gqa + 8 < SLEN) {
            __half2 hv = {__float2half_rn(oacc[nt][2] * inv1),
                          __float2half_rn(oacc[nt][3] * inv1)};
            *(__half2*)(Oh + (rowBase + gqa + 8) * NSTATE + d) = hv;
        }
    }
}

// ---------------- launch -----------------------------------------------------
extern "C" void kernel_launch(void* const* d_in, const int* in_sizes, int n_in,
                              void* d_out, int out_size)
{
    const float* x  = (const float*)d_in[0];
    const float* Wq = (const float*)d_in[2];
    const float* bq = (const float*)d_in[3];
    const float* Wk = (const float*)d_in[4];
    const float* Wv = (const float*)d_in[5];
    const float* bv = (const float*)d_in[6];
    const float* Wo = (const float*)d_in[7];
    const float* bo = (const float*)d_in[8];
    float* out = (float*)d_out;

    __half *xh, *qh, *kh, *vh, *oh, *wh;
    cudaGetSymbolAddress((void**)&xh, g_Xh);
    cudaGetSymbolAddress((void**)&qh, g_Qh);
    cudaGetSymbolAddress((void**)&kh, g_Kh);
    cudaGetSymbolAddress((void**)&vh, g_Vh);
    cudaGetSymbolAddress((void**)&oh, g_Oh);
    cudaGetSymbolAddress((void**)&wh, g_Wh);
    const size_t WSZ = (size_t)NSTATE * NSTATE;

    cudaFuncSetAttribute(gemm_f16_kernel<0>,
                         cudaFuncAttributeMaxDynamicSharedMemorySize, GSMEM2);
    cudaFuncSetAttribute(gemm_f16_kernel<1>,
                         cudaFuncAttributeMaxDynamicSharedMemorySize, GSMEM2);
    cudaFuncSetAttribute(flash_hmma_kernel,
                         cudaFuncAttributeMaxDynamicSharedMemorySize, FSMEM);

    const int xn4 = MROWS * NSTATE / 4;
    const int wn4 = NSTATE * NSTATE / 4;
    cvt_f16_kernel<<<dim3((xn4 + 255) / 256, 1), 256>>>(
        x, nullptr, nullptr, nullptr, xh, 0, xn4);
    cvt_f16_kernel<<<dim3((wn4 + 255) / 256, 4), 256>>>(
        Wq, Wk, Wv, Wo, wh, WSZ, wn4);

    const dim3 qkvgrid(NSTATE / 128, (MROWS + 127) / 128, 3);
    gemm_f16_kernel<0><<<qkvgrid, 256, GSMEM2>>>(
        xh, wh, bq, bv, bo, qh, kh, vh, nullptr, MROWS);

    const dim3 agrid((SLEN + AQ - 1) / AQ, BATCH * NHEAD);   // 24 x 128
    flash_hmma_kernel<<<agrid, 128, FSMEM>>>(qh, kh, vh, oh);

    const dim3 ogrid(NSTATE / 128, (MROWS + 127) / 128, 1);
    gemm_f16_kernel<1><<<ogrid, 256, GSMEM2>>>(
        oh, wh, bq, bv, bo, nullptr, nullptr, nullptr, out, MROWS);
}

// round 14
// speedup vs baseline: 2.7798x; 1.0250x over previous
#include <cuda_runtime.h>
#include <cuda_bf16.h>
#include <cuda_fp16.h>
#include <cstdint>

#define BATCH  8
#define SLEN   1500
#define NSTATE 1024
#define NHEAD  16
#define HDIM   64
#define MROWS  (BATCH * SLEN)   // 12000

// scale folded into Q projection: 1/sqrt(64) * log2(e)
#define QSCALE 0.18033688011112042f
#define ONES_H2 0x3C003C00u     // half2(1.0, 1.0)

// ---------------- scratch (static device globals; no allocation) -------------
__device__ __half g_Xh[(size_t)MROWS * NSTATE];
__device__ __half g_Qh[(size_t)MROWS * NSTATE];
__device__ __half g_Kh[(size_t)MROWS * NSTATE];
__device__ __half g_Vh[(size_t)MROWS * NSTATE];
__device__ __half g_Oh[(size_t)MROWS * NSTATE];
__device__ __half g_Wh[4][(size_t)NSTATE * NSTATE];

__device__ __forceinline__ uint32_t smem_u32(const void* p) {
    uint32_t a;
    asm("{ .reg .u64 t; cvta.to.shared.u64 t, %1; cvt.u32.u64 %0, t; }"
        : "=r"(a) : "l"(p));
    return a;
}
__device__ __forceinline__ float ex2f(float x) {
    float r;
    asm("ex2.approx.f32 %0, %1;" : "=f"(r) : "f"(x));
    return r;
}

#define LDSM_X4(r0, r1, r2, r3, addr)                                            \
    asm volatile("ldmatrix.sync.aligned.m8n8.x4.shared.b16 {%0,%1,%2,%3}, [%4];" \
                 : "=r"(r0), "=r"(r1), "=r"(r2), "=r"(r3) : "r"(addr))

#define LDSM_X4_T(r0, r1, r2, r3, addr)                                          \
    asm volatile("ldmatrix.sync.aligned.m8n8.x4.trans.shared.b16 {%0,%1,%2,%3}, [%4];" \
                 : "=r"(r0), "=r"(r1), "=r"(r2), "=r"(r3) : "r"(addr))

#define MMA_F16(c0, c1, c2, c3, a0, a1, a2, a3, b0, b1)                          \
    asm volatile("mma.sync.aligned.m16n8k16.row.col.f32.f16.f16.f32 "            \
                 "{%0,%1,%2,%3}, {%4,%5,%6,%7}, {%8,%9}, {%0,%1,%2,%3};"         \
                 : "+f"(c0), "+f"(c1), "+f"(c2), "+f"(c3)                        \
                 : "r"(a0), "r"(a1), "r"(a2), "r"(a3), "r"(b0), "r"(b1))

#define PACK_H2(d, vlo, vhi)                                                     \
    asm("cvt.rn.f16x2.f32 %0, %1, %2;" : "=r"(d) : "f"(vhi), "f"(vlo))

#define EX2_H2(d, s)                                                             \
    asm("ex2.approx.f16x2 %0, %1;" : "=r"(d) : "r"(s))

#define CP16(dst, src, nbytes)                                                   \
    asm volatile("cp.async.cg.shared.global [%0], [%1], 16, %2;"                 \
                 :: "r"(dst), "l"(src), "r"(nbytes))
#define CP_COMMIT() asm volatile("cp.async.commit_group;" ::: "memory")
#define CP_WAIT0()  asm volatile("cp.async.wait_group 0;" ::: "memory")

// ======================= convert fp32 -> fp16 ================================
__global__ __launch_bounds__(256) void cvt_f16_kernel(
    const float* __restrict__ in0, const float* __restrict__ in1,
    const float* __restrict__ in2, const float* __restrict__ in3,
    __half* __restrict__ o, size_t zstride, int n4)
{
    const int z = blockIdx.y;
    const float* in = (z == 0) ? in0 : (z == 1) ? in1 : (z == 2) ? in2 : in3;
    o += z * zstride;
    int i = blockIdx.x * blockDim.x + threadIdx.x;
    if (i < n4) {
        float4 v = *(const float4*)(in + (size_t)i * 4);
        __half2 h0 = {__float2half_rn(v.x), __float2half_rn(v.y)};
        __half2 h1 = {__float2half_rn(v.z), __float2half_rn(v.w)};
        *(__half2*)(o + (size_t)i * 4)     = h0;
        *(__half2*)(o + (size_t)i * 4 + 2) = h1;
    }
}

// ===== fp16 single-MMA GEMM (2-stage cp.async, BK=64, 1 barrier/iter) ========
#define GBK     64
#define GPAD    72
#define GK_ITERS (NSTATE / GBK)            // 16
#define ARR_B   (128 * GPAD * 2)           // 18432 bytes per array
#define STG2_B  (2 * ARR_B)                // 36864 bytes per stage
#define GSMEM2  (2 * STG2_B)               // 73728 bytes

template <int PASS>
__global__ __launch_bounds__(256) void gemm_f16_kernel(
    const __half* __restrict__ A, const __half* __restrict__ W,
    const float* __restrict__ bq, const float* __restrict__ bv,
    const float* __restrict__ bo,
    __half* __restrict__ outQ, __half* __restrict__ outK,
    __half* __restrict__ outV, float* __restrict__ outF, int M)
{
    extern __shared__ __align__(16) char dsm[];
    const int z = (PASS == 0) ? blockIdx.z : 3;
    const __half* B = W + (size_t)z * NSTATE * NSTATE;
    const float* bias = (PASS == 1) ? bo : ((z == 0) ? bq : (z == 2) ? bv : nullptr);

    const int tid  = threadIdx.x;
    const int wid  = tid >> 5;
    const int lane = tid & 31;
    const int m0 = blockIdx.y * 128;
    const int n0 = blockIdx.x * 128;
    const int mbase = (wid >> 2) * 64;
    const int nbase = (wid & 3) * 32;
    const uint32_t uBase = smem_u32(dsm);

    float acc[4][4][4];
#pragma unroll
    for (int i = 0; i < 4; i++)
#pragma unroll
        for (int j = 0; j < 4; j++)
#pragma unroll
            for (int q = 0; q < 4; q++) acc[i][j][q] = 0.f;

    const int lrow = tid >> 3;
    const int lc   = (tid & 7) * 8;
    int      okA[4];
    size_t   ga[4], gb[4];
    uint32_t so[4];
#pragma unroll
    for (int i = 0; i < 4; i++) {
        const int r = lrow + i * 32;
        okA[i] = (m0 + r < M) ? 16 : 0;
        ga[i]  = (size_t)(m0 + r) * NSTATE + lc;
        gb[i]  = (size_t)(n0 + r) * NSTATE + lc;
        so[i]  = (uint32_t)(r * GPAD + lc) * 2;
    }

#define ISSUE2(kit, stg) do {                                                    \
        const int k0_ = (kit) * GBK;                                             \
        const uint32_t sb = uBase + (stg) * STG2_B;                              \
        _Pragma("unroll")                                                        \
        for (int i = 0; i < 4; i++)                                              \
            CP16(sb + 0 * ARR_B + so[i], A + ga[i] + k0_, okA[i]);               \
        _Pragma("unroll")                                                        \
        for (int i = 0; i < 4; i++)                                              \
            CP16(sb + 1 * ARR_B + so[i], B + gb[i] + k0_, 16);                   \
        CP_COMMIT();                                                             \
    } while (0)

    ISSUE2(0, 0);

    const int aRow = lane & 15, aKof = (lane >> 4) * 8;
    const int bNof = ((lane >> 4) * 8) + (lane & 7);
    const int bKof = ((lane >> 3) & 1) * 8;

    for (int kit = 0; kit < GK_ITERS; kit++) {
        // single barrier per iteration: wait stage-k data, publish, then
        // prefetch k+1 (writes the *other* stage, whose last readers all
        // passed this barrier in iteration k-1) while computing k.
        CP_WAIT0();
        __syncthreads();
        if (kit + 1 < GK_ITERS) ISSUE2(kit + 1, (kit + 1) & 1);

        const uint32_t sb = uBase + (kit & 1) * STG2_B;
        const uint32_t uA = sb, uB = sb + ARR_B;
#pragma unroll
        for (int ks = 0; ks < 4; ks++) {
            const int kof = ks * 16;
            uint32_t a[4][4];
#pragma unroll
            for (int mt = 0; mt < 4; mt++) {
                const uint32_t off =
                    (uint32_t)((mbase + mt * 16 + aRow) * GPAD + kof + aKof) * 2;
                LDSM_X4(a[mt][0], a[mt][1], a[mt][2], a[mt][3], uA + off);
            }
            uint32_t b[4][2];
#pragma unroll
            for (int np = 0; np < 2; np++) {
                const uint32_t off =
                    (uint32_t)((nbase + np * 16 + bNof) * GPAD + kof + bKof) * 2;
                LDSM_X4(b[np * 2][0], b[np * 2][1], b[np * 2 + 1][0], b[np * 2 + 1][1],
                        uB + off);
            }
#pragma unroll
            for (int mt = 0; mt < 4; mt++)
#pragma unroll
                for (int nt = 0; nt < 4; nt++) {
                    float* c4 = acc[mt][nt];
                    MMA_F16(c4[0], c4[1], c4[2], c4[3],
                            a[mt][0], a[mt][1], a[mt][2], a[mt][3],
                            b[nt][0], b[nt][1]);
                }
        }
    }
#undef ISSUE2

    const int lr = lane >> 2;
    const int lc2 = (lane & 3) * 2;
#pragma unroll
    for (int mt = 0; mt < 4; mt++) {
#pragma unroll
        for (int half_ = 0; half_ < 2; half_++) {
            const int gm = m0 + mbase + mt * 16 + half_ * 8 + lr;
            if (gm < M) {
#pragma unroll
                for (int nt = 0; nt < 4; nt++) {
                    const int gn = n0 + nbase + nt * 8 + lc2;
                    float vx = acc[mt][nt][half_ * 2 + 0];
                    float vy = acc[mt][nt][half_ * 2 + 1];
                    if (bias) { vx += bias[gn]; vy += bias[gn + 1]; }
                    if (PASS == 0 && z == 0) { vx *= QSCALE; vy *= QSCALE; }
                    const size_t idx = (size_t)gm * NSTATE + gn;
                    if (PASS == 1) {
                        *(float2*)(outF + idx) = make_float2(vx, vy);
                    } else {
                        __half2 hv = {__float2half_rn(vx), __float2half_rn(vy)};
                        __half* o = (z == 0) ? outQ : (z == 1) ? outK : outV;
                        *(__half2*)(o + idx) = hv;
                    }
                }
            }
        }
    }
}

// ================= fp16 HMMA flash attention (causal, 1 barrier/tile) ========
#define AQ    64
#define AKV   64
#define APAD  72
#define FARR  (AKV * APAD * 2)     // 9216 bytes per K/V array
#define FSTG  (2 * FARR)           // 18432 bytes per stage (K, V)
#define FSMEM (2 * FSTG)           // 36864 bytes

__global__ __launch_bounds__(128, 4) void flash_hmma_kernel(
    const __half* __restrict__ Qh, const __half* __restrict__ Kh,
    const __half* __restrict__ Vh, __half* __restrict__ Oh)
{
    extern __shared__ __align__(16) char fsm[];
    const uint32_t uS = smem_u32(fsm);

    const int tid  = threadIdx.x;
    const int wid  = tid >> 5;
    const int lane = tid & 31;
    const int bh = blockIdx.y;
    const int b  = bh >> 4;
    const int h  = bh & 15;
    const int q0 = (gridDim.x - 1 - blockIdx.x) * AQ;   // longest CTAs first
    const size_t rowBase = (size_t)b * SLEN;
    const int colOff = h * HDIM;

    // ---- stage Q tile (64x64 fp16) ----
#pragma unroll
    for (int it = 0; it < 4; it++) {
        const int id = tid + it * 128;
        const int r  = id >> 3;
        const int c  = id & 7;
        const int gq = q0 + r;
        uint4 v = make_uint4(0, 0, 0, 0);
        if (gq < SLEN)
            v = *(const uint4*)(Qh + (rowBase + gq) * NSTATE + colOff + c * 8);
        *(uint4*)(fsm + (r * APAD + c * 8) * 2) = v;
    }
    __syncthreads();

    const int aRow = lane & 15, aKof = (lane >> 4) * 8;
    const int wq0 = wid * 16;
    uint32_t qf[4][4];
#pragma unroll
    for (int ks = 0; ks < 4; ks++) {
        const uint32_t off = (uint32_t)((wq0 + aRow) * APAD + ks * 16 + aKof) * 2;
        LDSM_X4(qf[ks][0], qf[ks][1], qf[ks][2], qf[ks][3], uS + off);
    }
    __syncthreads();

#define FA_ISSUE(t, stg) do {                                                    \
        const int j0_ = (t) * AKV;                                               \
        const uint32_t sb = uS + (stg) * FSTG;                                   \
        _Pragma("unroll")                                                        \
        for (int it = 0; it < 4; it++) {                                         \
            const int id = tid + it * 128;                                       \
            const int r  = id >> 3;                                              \
            const int c  = id & 7;                                               \
            const int gk = j0_ + r;                                              \
            const int nb = (gk < SLEN) ? 16 : 0;                                 \
            const size_t off = (rowBase + gk) * NSTATE + colOff + c * 8;         \
            const uint32_t so_ = (uint32_t)(r * APAD + c * 8) * 2;               \
            CP16(sb + 0 * FARR + so_, Kh + off, nb);                             \
            CP16(sb + 1 * FARR + so_, Vh + off, nb);                             \
        }                                                                        \
        CP_COMMIT();                                                             \
    } while (0)

    const int gqa = q0 + wq0 + (lane >> 2);
    float mr0 = -1e30f, mr1 = -1e30f, l0 = 0.f, l1 = 0.f;
    float oacc[8][4];
#pragma unroll
    for (int i = 0; i < 8; i++)
#pragma unroll
        for (int q = 0; q < 4; q++) oacc[i][q] = 0.f;

    const int bNof = ((lane >> 4) * 8) + (lane & 7);
    const int bKof = ((lane >> 3) & 1) * 8;
    const int vRow = ((lane >> 3) & 1) * 8 + (lane & 7);
    const int vCof = (lane >> 4) * 8;

    const int tEnd = min(q0 + AQ - 1, SLEN - 1) / AKV;
    FA_ISSUE(0, 0);

    for (int t = 0; t <= tEnd; t++) {
        const int j0 = t * AKV;
        // single barrier per tile: wait stage-t data, publish, then prefetch
        // t+1 into the other stage (its last readers passed this barrier).
        CP_WAIT0();
        __syncthreads();
        if (t + 1 <= tEnd) FA_ISSUE(t + 1, (t + 1) & 1);

        const uint32_t sb = uS + (t & 1) * FSTG;
        const uint32_t uK = sb, uV = sb + FARR;

        if (j0 <= q0 + wq0 + 15) {
            // ---- S = Q K^T (fp16, Q pre-scaled to base-2 domain) ----
            float S[8][4];
#pragma unroll
            for (int nt = 0; nt < 8; nt++)
#pragma unroll
                for (int q = 0; q < 4; q++) S[nt][q] = 0.f;
#pragma unroll
            for (int ks = 0; ks < 4; ks++) {
                uint32_t kf[8][2];
#pragma unroll
                for (int np = 0; np < 4; np++) {
                    const uint32_t off =
                        (uint32_t)((np * 16 + bNof) * APAD + ks * 16 + bKof) * 2;
                    LDSM_X4(kf[np * 2][0], kf[np * 2][1],
                            kf[np * 2 + 1][0], kf[np * 2 + 1][1], uK + off);
                }
#pragma unroll
                for (int nt = 0; nt < 8; nt++)
                    MMA_F16(S[nt][0], S[nt][1], S[nt][2], S[nt][3],
                            qf[ks][0], qf[ks][1], qf[ks][2], qf[ks][3],
                            kf[nt][0], kf[nt][1]);
            }
            // ---- masking + row max ----
            const bool needMask = (j0 + AKV - 1 > q0 + wq0) || (j0 + AKV > SLEN);
            float mx0 = mr0, mx1 = mr1;
            if (needMask) {
                const int jc = j0 + 2 * (lane & 3);
#pragma unroll
                for (int nt = 0; nt < 8; nt++) {
#pragma unroll
                    for (int q = 0; q < 4; q++) {
                        const int jg  = jc + nt * 8 + (q & 1);
                        const int row = (q < 2) ? gqa : gqa + 8;
                        const bool ok = (jg <= row) && (jg < SLEN);
                        const float sv = ok ? S[nt][q] : -1e30f;
                        S[nt][q] = sv;
                        if (q < 2) mx0 = fmaxf(mx0, sv); else mx1 = fmaxf(mx1, sv);
                    }
                }
            } else {
#pragma unroll
                for (int nt = 0; nt < 8; nt++) {
                    mx0 = fmaxf(mx0, fmaxf(S[nt][0], S[nt][1]));
                    mx1 = fmaxf(mx1, fmaxf(S[nt][2], S[nt][3]));
                }
            }
            mx0 = fmaxf(mx0, __shfl_xor_sync(0xffffffffu, mx0, 1));
            mx0 = fmaxf(mx0, __shfl_xor_sync(0xffffffffu, mx0, 2));
            mx1 = fmaxf(mx1, __shfl_xor_sync(0xffffffffu, mx1, 1));
            mx1 = fmaxf(mx1, __shfl_xor_sync(0xffffffffu, mx1, 2));
            const float corr0 = ex2f(mr0 - mx0);
            const float corr1 = ex2f(mr1 - mx1);
            mr0 = mx0; mr1 = mx1;

            // ---- sub(max) in fp32, pack half2, packed ex2 -> P fragments ----
            uint32_t Pl[8], Ph[8];
#pragma unroll
            for (int nt = 0; nt < 8; nt++) {
                uint32_t plo, phi;
                PACK_H2(plo, S[nt][0] - mx0, S[nt][1] - mx0);
                PACK_H2(phi, S[nt][2] - mx1, S[nt][3] - mx1);
                EX2_H2(Pl[nt], plo);
                EX2_H2(Ph[nt], phi);
            }
            // ---- row sums via ones-MMA (cross-thread reduction on tensor pipe)
            float sc0 = 0.f, sc1 = 0.f, sc2 = 0.f, sc3 = 0.f;
#pragma unroll
            for (int ks2 = 0; ks2 < 4; ks2++)
                MMA_F16(sc0, sc1, sc2, sc3,
                        Pl[2 * ks2], Ph[2 * ks2], Pl[2 * ks2 + 1], Ph[2 * ks2 + 1],
                        ONES_H2, ONES_H2);
            l0 = l0 * corr0 + sc0;
            l1 = l1 * corr1 + sc2;
#pragma unroll
            for (int nt = 0; nt < 8; nt++) {
                oacc[nt][0] *= corr0; oacc[nt][1] *= corr0;
                oacc[nt][2] *= corr1; oacc[nt][3] *= corr1;
            }
            // ---- O += P V (fragments already packed) ----
#pragma unroll
            for (int ks2 = 0; ks2 < 4; ks2++) {
                const uint32_t a0 = Pl[2 * ks2],     a1 = Ph[2 * ks2];
                const uint32_t a2 = Pl[2 * ks2 + 1], a3 = Ph[2 * ks2 + 1];
#pragma unroll
                for (int dp = 0; dp < 4; dp++) {
                    uint32_t v0, v1, v2, v3;
                    const uint32_t off =
                        (uint32_t)((ks2 * 16 + vRow) * APAD + dp * 16 + vCof) * 2;
                    LDSM_X4_T(v0, v1, v2, v3, uV + off);
                    MMA_F16(oacc[2 * dp][0], oacc[2 * dp][1],
                            oacc[2 * dp][2], oacc[2 * dp][3],
                            a0, a1, a2, a3, v0, v1);
                    MMA_F16(oacc[2 * dp + 1][0], oacc[2 * dp + 1][1],
                            oacc[2 * dp + 1][2], oacc[2 * dp + 1][3],
                            a0, a1, a2, a3, v2, v3);
                }
            }
        }
    }
#undef FA_ISSUE

    const float inv0 = (l0 > 0.f) ? 1.f / l0 : 0.f;
    const float inv1 = (l1 > 0.f) ? 1.f / l1 : 0.f;
#pragma unroll
    for (int nt = 0; nt < 8; nt++) {
        const int d = colOff + nt * 8 + 2 * (lane & 3);
        if (gqa < SLEN) {
            __half2 hv = {__float2half_rn(oacc[nt][0] * inv0),
                          __float2half_rn(oacc[nt][1] * inv0)};
            *(__half2*)(Oh + (rowBase + gqa) * NSTATE + d) = hv;
        }
        if (gqa + 8 < SLEN) {
            __half2 hv = {__float2half_rn(oacc[nt][2] * inv1),
                          __float2half_rn(oacc[nt][3] * inv1)};
            *(__half2*)(Oh + (rowBase + gqa + 8) * NSTATE + d) = hv;
        }
    }
}

// ---------------- launch -----------------------------------------------------
extern "C" void kernel_launch(void* const* d_in, const int* in_sizes, int n_in,
                              void* d_out, int out_size)
{
    const float* x  = (const float*)d_in[0];
    const float* Wq = (const float*)d_in[2];
    const float* bq = (const float*)d_in[3];
    const float* Wk = (const float*)d_in[4];
    const float* Wv = (const float*)d_in[5];
    const float* bv = (const float*)d_in[6];
    const float* Wo = (const float*)d_in[7];
    const float* bo = (const float*)d_in[8];
    float* out = (float*)d_out;

    __half *xh, *qh, *kh, *vh, *oh, *wh;
    cudaGetSymbolAddress((void**)&xh, g_Xh);
    cudaGetSymbolAddress((void**)&qh, g_Qh);
    cudaGetSymbolAddress((void**)&kh, g_Kh);
    cudaGetSymbolAddress((void**)&vh, g_Vh);
    cudaGetSymbolAddress((void**)&oh, g_Oh);
    cudaGetSymbolAddress((void**)&wh, g_Wh);
    const size_t WSZ = (size_t)NSTATE * NSTATE;

    cudaFuncSetAttribute(gemm_f16_kernel<0>,
                         cudaFuncAttributeMaxDynamicSharedMemorySize, GSMEM2);
    cudaFuncSetAttribute(gemm_f16_kernel<1>,
                         cudaFuncAttributeMaxDynamicSharedMemorySize, GSMEM2);
    cudaFuncSetAttribute(flash_hmma_kernel,
                         cudaFuncAttributeMaxDynamicSharedMemorySize, FSMEM);

    const int xn4 = MROWS * NSTATE / 4;
    const int wn4 = NSTATE * NSTATE / 4;
    cvt_f16_kernel<<<dim3((xn4 + 255) / 256, 1), 256>>>(
        x, nullptr, nullptr, nullptr, xh, 0, xn4);
    cvt_f16_kernel<<<dim3((wn4 + 255) / 256, 4), 256>>>(
        Wq, Wk, Wv, Wo, wh, WSZ, wn4);

    const dim3 qkvgrid(NSTATE / 128, (MROWS + 127) / 128, 3);
    gemm_f16_kernel<0><<<qkvgrid, 256, GSMEM2>>>(
        xh, wh, bq, bv, bo, qh, kh, vh, nullptr, MROWS);

    const dim3 agrid((SLEN + AQ - 1) / AQ, BATCH * NHEAD);   // 24 x 128
    flash_hmma_kernel<<<agrid, 128, FSMEM>>>(qh, kh, vh, oh);

    const dim3 ogrid(NSTATE / 128, (MROWS + 127) / 128, 1);
    gemm_f16_kernel<1><<<ogrid, 256, GSMEM2>>>(
        oh, wh, bq, bv, bo, nullptr, nullptr, nullptr, out, MROWS);
}